// round 9
// baseline (speedup 1.0000x reference)
#include <cuda_runtime.h>
#include <cuda_bf16.h>
#include <math.h>
#include <stdint.h>

// Problem constants
#define B_   256
#define S_   128
#define P_   100
#define N_   500
#define E_   256
#define H_   4
#define HD_  64
#define L_   2
#define F_   1024
#define T_   (B_ * S_)      // 32768 tokens
#define NT_  (P_ + N_)      // 600 targets

// ---------------------------------------------------------------------------
// Scratch (device globals — no allocation allowed)
// ---------------------------------------------------------------------------
__device__ float g_x   [(size_t)T_ * E_];
__device__ float g_qkv [(size_t)T_ * 3 * E_];
__device__ float g_attn[(size_t)T_ * E_];
__device__ float g_ff  [(size_t)T_ * F_];

// ---------------------------------------------------------------------------
// cp.async + tf32 helpers
// ---------------------------------------------------------------------------
__device__ __forceinline__ void cp16(void* sdst, const void* gsrc) {
    uint32_t s = (uint32_t)__cvta_generic_to_shared(sdst);
    asm volatile("cp.async.cg.shared.global [%0], [%1], 16;\n" :: "r"(s), "l"(gsrc));
}
__device__ __forceinline__ void cp_commit() {
    asm volatile("cp.async.commit_group;\n");
}
template<int NWait>
__device__ __forceinline__ void cp_wait() {
    asm volatile("cp.async.wait_group %0;\n" :: "n"(NWait));
}
__device__ __forceinline__ uint32_t f2tf32(float x) {
    uint32_t r;
    asm("cvt.rna.tf32.f32 %0, %1;" : "=r"(r) : "f"(x));
    return r;
}
#define MMA_TF32(d, a, b)                                                     \
    asm volatile(                                                             \
        "mma.sync.aligned.m16n8k8.row.col.f32.tf32.tf32.f32 "                 \
        "{%0,%1,%2,%3}, {%4,%5,%6,%7}, {%8,%9}, {%0,%1,%2,%3};"               \
        : "+f"(d[0]), "+f"(d[1]), "+f"(d[2]), "+f"(d[3])                      \
        : "r"(a[0]), "r"(a[1]), "r"(a[2]), "r"(a[3]), "r"(b[0]), "r"(b[1]))

// ---------------------------------------------------------------------------
// Embedding gather (float4)
// ---------------------------------------------------------------------------
__global__ void gather_kernel(const int* __restrict__ attr,
                              const float* __restrict__ emb,
                              float* __restrict__ x) {
    int i4 = blockIdx.x * blockDim.x + threadIdx.x;
    if (i4 < T_ * (E_ / 4)) {
        int t = i4 >> 6;
        int e4 = i4 & 63;
        ((float4*)x)[i4] = ((const float4*)emb)[(size_t)attr[t] * (E_ / 4) + e4];
    }
}

// ---------------------------------------------------------------------------
// TF32 GEMM: C = A @ B^T + bias (opt ReLU). Block 128x128, BK=16, 8 warps
// of 64x32, 3-stage cp.async, 2 CTAs/SM. Used for QKV and FF1.
// ---------------------------------------------------------------------------
#define LDA    20
#define TSZ    (128 * LDA)
#define STAGES 3

template<bool RELU>
__global__ __launch_bounds__(256, 2)
void tgemm(const float* __restrict__ A, const float* __restrict__ Bm,
           const float* __restrict__ bias, float* __restrict__ C,
           int M, int N, int K) {
    extern __shared__ float smw[];
    float* As = smw;
    float* Bs = smw + STAGES * TSZ;

    const int bm   = blockIdx.y * 128;
    const int bn   = blockIdx.x * 128;
    const int t    = threadIdx.x;
    const int lane = t & 31;
    const int wid  = t >> 5;
    const int wm   = (wid & 1) * 64;
    const int wn   = (wid >> 1) * 32;
    const int g    = lane >> 2;
    const int tg   = lane & 3;

    const int lrow = t >> 1;
    const int lkb  = (t & 1) * 8;
    const float* Ap = A  + (size_t)(bm + lrow) * K + lkb;
    const float* Bp = Bm + (size_t)(bn + lrow) * K + lkb;

    float acc[4][4][4];
#pragma unroll
    for (int i = 0; i < 4; i++)
#pragma unroll
        for (int j = 0; j < 4; j++)
#pragma unroll
            for (int r = 0; r < 4; r++) acc[i][j][r] = 0.f;

    const int nk = K >> 4;
#pragma unroll
    for (int s = 0; s < STAGES - 1; s++) {
        const int k0 = s << 4;
        cp16(&As[s * TSZ + lrow * LDA + lkb],     Ap + k0);
        cp16(&As[s * TSZ + lrow * LDA + lkb + 4], Ap + k0 + 4);
        cp16(&Bs[s * TSZ + lrow * LDA + lkb],     Bp + k0);
        cp16(&Bs[s * TSZ + lrow * LDA + lkb + 4], Bp + k0 + 4);
        cp_commit();
    }

    int cur = 0;
    for (int kt = 0; kt < nk; kt++) {
        if (kt < nk - 1) cp_wait<STAGES - 2>(); else cp_wait<0>();
        __syncthreads();

        const float* Ac = As + cur * TSZ;
        const float* Bc = Bs + cur * TSZ;
#pragma unroll
        for (int ks = 0; ks < 2; ks++) {
            const int k0 = ks * 8;
            uint32_t af[4][4], bf[4][2];
#pragma unroll
            for (int mf = 0; mf < 4; mf++) {
                const int row = wm + mf * 16 + g;
                af[mf][0] = f2tf32(Ac[row * LDA + k0 + tg]);
                af[mf][1] = f2tf32(Ac[(row + 8) * LDA + k0 + tg]);
                af[mf][2] = f2tf32(Ac[row * LDA + k0 + tg + 4]);
                af[mf][3] = f2tf32(Ac[(row + 8) * LDA + k0 + tg + 4]);
            }
#pragma unroll
            for (int nf = 0; nf < 4; nf++) {
                const int col = wn + nf * 8 + g;
                bf[nf][0] = f2tf32(Bc[col * LDA + k0 + tg]);
                bf[nf][1] = f2tf32(Bc[col * LDA + k0 + tg + 4]);
            }
#pragma unroll
            for (int mf = 0; mf < 4; mf++)
#pragma unroll
                for (int nf = 0; nf < 4; nf++) MMA_TF32(acc[mf][nf], af[mf], bf[nf]);
        }

        const int pf = kt + STAGES - 1;
        if (pf < nk) {
            const int ps = pf % STAGES;
            const int k0 = pf << 4;
            cp16(&As[ps * TSZ + lrow * LDA + lkb],     Ap + k0);
            cp16(&As[ps * TSZ + lrow * LDA + lkb + 4], Ap + k0 + 4);
            cp16(&Bs[ps * TSZ + lrow * LDA + lkb],     Bp + k0);
            cp16(&Bs[ps * TSZ + lrow * LDA + lkb + 4], Bp + k0 + 4);
            cp_commit();
        }
        cur = (cur + 1 == STAGES) ? 0 : cur + 1;
    }

#pragma unroll
    for (int nf = 0; nf < 4; nf++) {
        const int col = bn + wn + nf * 8 + 2 * tg;
        const float b0v = bias[col], b1v = bias[col + 1];
#pragma unroll
        for (int mf = 0; mf < 4; mf++) {
            const int row = bm + wm + mf * 16 + g;
            float v0 = acc[mf][nf][0] + b0v;
            float v1 = acc[mf][nf][1] + b1v;
            float v2 = acc[mf][nf][2] + b0v;
            float v3 = acc[mf][nf][3] + b1v;
            if (RELU) {
                v0 = fmaxf(v0, 0.f); v1 = fmaxf(v1, 0.f);
                v2 = fmaxf(v2, 0.f); v3 = fmaxf(v3, 0.f);
            }
            *(float2*)(C + (size_t)row * N + col)       = make_float2(v0, v1);
            *(float2*)(C + (size_t)(row + 8) * N + col) = make_float2(v2, v3);
        }
    }
}

// ---------------------------------------------------------------------------
// TF32 GEMM + residual + LayerNorm, N fixed = 256 (full output rows/block).
// out[row] = LN(resid[row] + A[row]@B^T + bias) * lns + lnb
// Block 128x256 (R5-proven shape), 8 warps of 64x64, 3-stage cp.async.
// Row LN stats: quad-shfl partials -> smem[128][4] -> mean/rstd.
// resid/out may alias (block owns its 128 rows exclusively; all resid reads
// complete before the stats barrier, writes after).
// ---------------------------------------------------------------------------
#define ASZ2 (128 * LDA)
#define BSZ2 (256 * LDA)

__global__ __launch_bounds__(256)
void tgemm_ln256(const float* __restrict__ A, const float* __restrict__ Bm,
                 const float* __restrict__ bias,
                 const float* resid, const float* __restrict__ lns,
                 const float* __restrict__ lnb, float* out, int K) {
    extern __shared__ float smw[];
    float* As = smw;                      // [STAGES][128][LDA]
    float* Bs = smw + STAGES * ASZ2;      // [STAGES][256][LDA]

    const int bm   = blockIdx.x * 128;
    const int t    = threadIdx.x;
    const int lane = t & 31;
    const int wid  = t >> 5;
    const int wm   = (wid & 1) * 64;
    const int wn   = (wid >> 1) * 64;
    const int g    = lane >> 2;
    const int tg   = lane & 3;

    const int lrow = t >> 1;            // 0..127 (A rows)
    const int lkb  = (t & 1) * 8;
    const float* Ap = A  + (size_t)(bm + lrow) * K + lkb;
    const float* Bp = Bm + (size_t)t * K;   // 256 B rows, 16 k each

    float acc[4][8][4];
#pragma unroll
    for (int i = 0; i < 4; i++)
#pragma unroll
        for (int j = 0; j < 8; j++)
#pragma unroll
            for (int r = 0; r < 4; r++) acc[i][j][r] = 0.f;

    const int nk = K >> 4;
#pragma unroll
    for (int s = 0; s < STAGES - 1; s++) {
        const int k0 = s << 4;
        cp16(&As[s * ASZ2 + lrow * LDA + lkb],     Ap + k0);
        cp16(&As[s * ASZ2 + lrow * LDA + lkb + 4], Ap + k0 + 4);
#pragma unroll
        for (int j = 0; j < 4; j++)
            cp16(&Bs[s * BSZ2 + t * LDA + j * 4], Bp + k0 + j * 4);
        cp_commit();
    }

    int cur = 0;
    for (int kt = 0; kt < nk; kt++) {
        if (kt < nk - 1) cp_wait<STAGES - 2>(); else cp_wait<0>();
        __syncthreads();

        const float* Ac = As + cur * ASZ2;
        const float* Bc = Bs + cur * BSZ2;
#pragma unroll
        for (int ks = 0; ks < 2; ks++) {
            const int k0 = ks * 8;
            uint32_t af[4][4], bf[8][2];
#pragma unroll
            for (int mf = 0; mf < 4; mf++) {
                const int row = wm + mf * 16 + g;
                af[mf][0] = f2tf32(Ac[row * LDA + k0 + tg]);
                af[mf][1] = f2tf32(Ac[(row + 8) * LDA + k0 + tg]);
                af[mf][2] = f2tf32(Ac[row * LDA + k0 + tg + 4]);
                af[mf][3] = f2tf32(Ac[(row + 8) * LDA + k0 + tg + 4]);
            }
#pragma unroll
            for (int nf = 0; nf < 8; nf++) {
                const int col = wn + nf * 8 + g;
                bf[nf][0] = f2tf32(Bc[col * LDA + k0 + tg]);
                bf[nf][1] = f2tf32(Bc[col * LDA + k0 + tg + 4]);
            }
#pragma unroll
            for (int mf = 0; mf < 4; mf++)
#pragma unroll
                for (int nf = 0; nf < 8; nf++) MMA_TF32(acc[mf][nf], af[mf], bf[nf]);
        }

        const int pf = kt + STAGES - 1;
        if (pf < nk) {
            const int ps = pf % STAGES;
            const int k0 = pf << 4;
            cp16(&As[ps * ASZ2 + lrow * LDA + lkb],     Ap + k0);
            cp16(&As[ps * ASZ2 + lrow * LDA + lkb + 4], Ap + k0 + 4);
#pragma unroll
            for (int j = 0; j < 4; j++)
                cp16(&Bs[ps * BSZ2 + t * LDA + j * 4], Bp + k0 + j * 4);
            cp_commit();
        }
        cur = (cur + 1 == STAGES) ? 0 : cur + 1;
    }

    __syncthreads();   // fragment reads done; smem reused for LN stats

    float* rsum  = smw;              // [128][4]
    float* rsq   = smw + 512;        // [128][4]
    float* rmean = smw + 1024;       // [128]
    float* rrstd = smw + 1152;       // [128]
    const int nidx = wid >> 1;       // n-warp index 0..3

    // bias + residual into acc; per-row partials over this thread's 16 cols
#pragma unroll
    for (int mf = 0; mf < 4; mf++) {
        const int r0 = wm + mf * 16 + g;
        const int r1 = r0 + 8;
        float s0 = 0.f, q0 = 0.f, s1 = 0.f, q1 = 0.f;
#pragma unroll
        for (int nf = 0; nf < 8; nf++) {
            const int col = wn + nf * 8 + 2 * tg;
            const float b0v = bias[col], b1v = bias[col + 1];
            const float2 e0 = *(const float2*)(resid + (size_t)(bm + r0) * E_ + col);
            const float2 e1 = *(const float2*)(resid + (size_t)(bm + r1) * E_ + col);
            float* d = acc[mf][nf];
            d[0] += b0v + e0.x;  d[1] += b1v + e0.y;
            d[2] += b0v + e1.x;  d[3] += b1v + e1.y;
            s0 += d[0] + d[1];   q0 += d[0] * d[0] + d[1] * d[1];
            s1 += d[2] + d[3];   q1 += d[2] * d[2] + d[3] * d[3];
        }
#pragma unroll
        for (int o = 1; o < 4; o <<= 1) {
            s0 += __shfl_xor_sync(0xffffffffu, s0, o);
            q0 += __shfl_xor_sync(0xffffffffu, q0, o);
            s1 += __shfl_xor_sync(0xffffffffu, s1, o);
            q1 += __shfl_xor_sync(0xffffffffu, q1, o);
        }
        if (tg == 0) {
            rsum[r0 * 4 + nidx] = s0;  rsq[r0 * 4 + nidx] = q0;
            rsum[r1 * 4 + nidx] = s1;  rsq[r1 * 4 + nidx] = q1;
        }
    }
    __syncthreads();

    if (t < 128) {
        const float s = rsum[t * 4] + rsum[t * 4 + 1] + rsum[t * 4 + 2] + rsum[t * 4 + 3];
        const float q = rsq[t * 4]  + rsq[t * 4 + 1]  + rsq[t * 4 + 2]  + rsq[t * 4 + 3];
        const float m = s * (1.f / E_);
        const float v = q * (1.f / E_) - m * m;
        rmean[t] = m;
        rrstd[t] = rsqrtf(v + 1e-5f);
    }
    __syncthreads();

#pragma unroll
    for (int mf = 0; mf < 4; mf++) {
        const int r0 = wm + mf * 16 + g;
        const int r1 = r0 + 8;
        const float m0 = rmean[r0], rs0 = rrstd[r0];
        const float m1 = rmean[r1], rs1 = rrstd[r1];
#pragma unroll
        for (int nf = 0; nf < 8; nf++) {
            const int col = wn + nf * 8 + 2 * tg;
            const float2 sc = *(const float2*)(lns + col);
            const float2 bi = *(const float2*)(lnb + col);
            const float* d = acc[mf][nf];
            *(float2*)(out + (size_t)(bm + r0) * E_ + col) =
                make_float2((d[0] - m0) * rs0 * sc.x + bi.x,
                            (d[1] - m0) * rs0 * sc.y + bi.y);
            *(float2*)(out + (size_t)(bm + r1) * E_ + col) =
                make_float2((d[2] - m1) * rs1 * sc.x + bi.x,
                            (d[3] - m1) * rs1 * sc.y + bi.y);
        }
    }
}

// ---------------------------------------------------------------------------
// Tensor-core attention (R8-proven): one block per (b,h), 256 threads.
// ---------------------------------------------------------------------------
#define QLD 68
#define PLD2 132
#define VT_OFF 0
#define Q_OFF  (64 * PLD2)
#define K_OFF  (Q_OFF + 128 * QLD)
#define P_OFF  Q_OFF
#define PART_OFF (K_OFF + 128 * QLD)
#define RSUM_OFF (PART_OFF + 512)
#define ATTN_SMEMF (RSUM_OFF + 128)

__global__ __launch_bounds__(256)
void attn_kernel(const float* __restrict__ qkv,
                 const int* __restrict__ lens,
                 float* __restrict__ out) {
    const int bh = blockIdx.x;
    const int b  = bh / H_;
    const int h  = bh % H_;
    extern __shared__ float sm[];

    const int t    = threadIdx.x;
    const int lane = t & 31;
    const int wid  = t >> 5;
    const int g    = lane >> 2;
    const int tg   = lane & 3;
    const int len  = lens[b];

    for (int i4 = t; i4 < S_ * HD_ / 4; i4 += 256) {
        const int s  = i4 >> 4;
        const int d4 = i4 & 15;
        const float4* base =
            (const float4*)(qkv + (size_t)(b * S_ + s) * (3 * E_) + h * HD_);
        float4 qv = base[d4];
        float4 kv = base[(E_ / 4) + d4];
        float4 vv = base[(2 * E_ / 4) + d4];
        *(float4*)&sm[Q_OFF + s * QLD + d4 * 4] = qv;
        *(float4*)&sm[K_OFF + s * QLD + d4 * 4] = kv;
        const int d0 = d4 * 4;
        sm[VT_OFF + (d0 + 0) * PLD2 + s] = vv.x;
        sm[VT_OFF + (d0 + 1) * PLD2 + s] = vv.y;
        sm[VT_OFF + (d0 + 2) * PLD2 + s] = vv.z;
        sm[VT_OFF + (d0 + 3) * PLD2 + s] = vv.w;
    }
    __syncthreads();

    const int wm = (wid & 1) * 64;
    const int wn = (wid >> 1) * 32;
    float acc[4][4][4];
#pragma unroll
    for (int i = 0; i < 4; i++)
#pragma unroll
        for (int j = 0; j < 4; j++)
#pragma unroll
            for (int r = 0; r < 4; r++) acc[i][j][r] = 0.f;

#pragma unroll
    for (int ks = 0; ks < 8; ks++) {
        const int k0 = ks * 8;
        uint32_t af[4][4], bf[4][2];
#pragma unroll
        for (int mf = 0; mf < 4; mf++) {
            const int row = wm + mf * 16 + g;
            af[mf][0] = f2tf32(sm[Q_OFF + row * QLD + k0 + tg]);
            af[mf][1] = f2tf32(sm[Q_OFF + (row + 8) * QLD + k0 + tg]);
            af[mf][2] = f2tf32(sm[Q_OFF + row * QLD + k0 + tg + 4]);
            af[mf][3] = f2tf32(sm[Q_OFF + (row + 8) * QLD + k0 + tg + 4]);
        }
#pragma unroll
        for (int nf = 0; nf < 4; nf++) {
            const int col = wn + nf * 8 + g;
            bf[nf][0] = f2tf32(sm[K_OFF + col * QLD + k0 + tg]);
            bf[nf][1] = f2tf32(sm[K_OFF + col * QLD + k0 + tg + 4]);
        }
#pragma unroll
        for (int mf = 0; mf < 4; mf++)
#pragma unroll
            for (int nf = 0; nf < 4; nf++) MMA_TF32(acc[mf][nf], af[mf], bf[nf]);
    }

    float rs[4][2];
#pragma unroll
    for (int mf = 0; mf < 4; mf++) { rs[mf][0] = 0.f; rs[mf][1] = 0.f; }
#pragma unroll
    for (int mf = 0; mf < 4; mf++) {
#pragma unroll
        for (int nf = 0; nf < 4; nf++) {
            const int c0 = wn + nf * 8 + 2 * tg;
            const int c1 = c0 + 1;
            float* d = acc[mf][nf];
            d[0] = (c0 < len) ? __expf(d[0] * 0.125f) : 0.f;
            d[1] = (c1 < len) ? __expf(d[1] * 0.125f) : 0.f;
            d[2] = (c0 < len) ? __expf(d[2] * 0.125f) : 0.f;
            d[3] = (c1 < len) ? __expf(d[3] * 0.125f) : 0.f;
            rs[mf][0] += d[0] + d[1];
            rs[mf][1] += d[2] + d[3];
        }
#pragma unroll
        for (int o = 1; o < 4; o <<= 1) {
            rs[mf][0] += __shfl_xor_sync(0xffffffffu, rs[mf][0], o);
            rs[mf][1] += __shfl_xor_sync(0xffffffffu, rs[mf][1], o);
        }
    }
    __syncthreads();

    const int nidx = wid >> 1;
#pragma unroll
    for (int mf = 0; mf < 4; mf++) {
        const int r0 = wm + mf * 16 + g;
        const int r1 = r0 + 8;
#pragma unroll
        for (int nf = 0; nf < 4; nf++) {
            const int c0 = wn + nf * 8 + 2 * tg;
            const float* d = acc[mf][nf];
            *(float2*)&sm[P_OFF + r0 * PLD2 + c0] = make_float2(d[0], d[1]);
            *(float2*)&sm[P_OFF + r1 * PLD2 + c0] = make_float2(d[2], d[3]);
        }
        if (tg == 0) {
            sm[PART_OFF + r0 * 4 + nidx] = rs[mf][0];
            sm[PART_OFF + r1 * 4 + nidx] = rs[mf][1];
        }
    }
    __syncthreads();

    if (t < 128) {
        const float s = sm[PART_OFF + t * 4] + sm[PART_OFF + t * 4 + 1] +
                        sm[PART_OFF + t * 4 + 2] + sm[PART_OFF + t * 4 + 3];
        sm[RSUM_OFF + t] = 1.f / s;
    }
    __syncthreads();

    const int wm2 = (wid & 3) * 32;
    const int wn2 = (wid >> 2) * 32;
    float acc2[2][4][4];
#pragma unroll
    for (int i = 0; i < 2; i++)
#pragma unroll
        for (int j = 0; j < 4; j++)
#pragma unroll
            for (int r = 0; r < 4; r++) acc2[i][j][r] = 0.f;

#pragma unroll
    for (int ks = 0; ks < 16; ks++) {
        const int k0 = ks * 8;
        uint32_t af[2][4], bf[4][2];
#pragma unroll
        for (int mf = 0; mf < 2; mf++) {
            const int row = wm2 + mf * 16 + g;
            af[mf][0] = f2tf32(sm[P_OFF + row * PLD2 + k0 + tg]);
            af[mf][1] = f2tf32(sm[P_OFF + (row + 8) * PLD2 + k0 + tg]);
            af[mf][2] = f2tf32(sm[P_OFF + row * PLD2 + k0 + tg + 4]);
            af[mf][3] = f2tf32(sm[P_OFF + (row + 8) * PLD2 + k0 + tg + 4]);
        }
#pragma unroll
        for (int nf = 0; nf < 4; nf++) {
            const int col = wn2 + nf * 8 + g;
            bf[nf][0] = f2tf32(sm[VT_OFF + col * PLD2 + k0 + tg]);
            bf[nf][1] = f2tf32(sm[VT_OFF + col * PLD2 + k0 + tg + 4]);
        }
#pragma unroll
        for (int mf = 0; mf < 2; mf++)
#pragma unroll
            for (int nf = 0; nf < 4; nf++) MMA_TF32(acc2[mf][nf], af[mf], bf[nf]);
    }

#pragma unroll
    for (int mf = 0; mf < 2; mf++) {
        const int r0 = wm2 + mf * 16 + g;
        const int r1 = r0 + 8;
        const float i0 = sm[RSUM_OFF + r0];
        const float i1 = sm[RSUM_OFF + r1];
#pragma unroll
        for (int nf = 0; nf < 4; nf++) {
            const int c = wn2 + nf * 8 + 2 * tg;
            const float* d = acc2[mf][nf];
            *(float2*)(out + (size_t)(b * S_ + r0) * E_ + h * HD_ + c) =
                make_float2(d[0] * i0, d[1] * i0);
            *(float2*)(out + (size_t)(b * S_ + r1) * E_ + h * HD_ + c) =
                make_float2(d[2] * i1, d[3] * i1);
        }
    }
}

// ---------------------------------------------------------------------------
// Head: pool + concat + 600-target scoring, one block per sample, 512 thr.
// ---------------------------------------------------------------------------
__global__ __launch_bounds__(512)
void head_kernel(const float* __restrict__ x, const float* __restrict__ attr_tf,
                 const int* __restrict__ lens, const int* __restrict__ lens_user,
                 const float* __restrict__ feat, const float* __restrict__ fW,
                 const float* __restrict__ fb,
                 const int* __restrict__ user_ids, const int* __restrict__ item_ids,
                 const float* __restrict__ user_emb, const float* __restrict__ item_emb,
                 const float* __restrict__ out_emb,
                 const int* __restrict__ pos_t, const int* __restrict__ pos_l,
                 const int* __restrict__ neg_t, const int* __restrict__ neg_l,
                 float* __restrict__ dout) {
    const int b    = blockIdx.x;
    const int t    = threadIdx.x;
    const int warp = t >> 5;
    const int lane = t & 31;
    __shared__ float ov[3 * E_];
    __shared__ float w[S_];
    __shared__ float part[2][E_];
    __shared__ float wu_s;

    if (t == 0) {
        float z = fb[0];
#pragma unroll
        for (int i = 0; i < 13; i++) z += feat[b * 13 + i] * fW[i];
        wu_s = 1.f / (1.f + expf(-z));
    }
    if (t < 256) {
        ov[t]           = user_emb[(size_t)user_ids[b] * E_ + t];
        ov[2 * E_ + t]  = item_emb[(size_t)item_ids[b] * E_ + t];
    }
    __syncthreads();
    if (t < S_) {
        float wgt = 0.f;
        if (t < lens[b]) {
            const float gte = (t < lens_user[b]) ? wu_s : (1.f - wu_s);
            wgt = attr_tf[b * S_ + t] * gte;
        }
        w[t] = wgt;
    }
    __syncthreads();
    {
        const int e    = t & 255;
        const int half = t >> 8;
        float acc = 0.f;
        const float* xb = x + (size_t)b * S_ * E_ + e;
        const int s0 = half * 64;
        for (int s = s0; s < s0 + 64; s++) acc += w[s] * xb[(size_t)s * E_];
        part[half][e] = acc;
    }
    __syncthreads();
    if (t < 256) ov[E_ + t] = part[0][t] + part[1][t];
    __syncthreads();

    const int pl = pos_l[b];
    const int nl = neg_l[b];
    const float4* ovs = (const float4*)ov;

    for (int j = warp; j < NT_; j += 32) {
        const int j2 = j + 16;
        int tgt1; float valid1, pos1;
        if (j < P_) {
            tgt1 = pos_t[b * P_ + j]; valid1 = (j < pl) ? 1.f : 0.f; pos1 = 1.f;
        } else {
            const int jn = j - P_;
            tgt1 = neg_t[b * N_ + jn]; valid1 = (jn < nl) ? 1.f : 0.f; pos1 = 0.f;
        }
        const bool have2 = (j2 < NT_);
        int tgt2 = 0; float valid2 = 0.f, pos2 = 0.f;
        if (have2) {
            if (j2 < P_) {
                tgt2 = pos_t[b * P_ + j2]; valid2 = (j2 < pl) ? 1.f : 0.f; pos2 = 1.f;
            } else {
                const int jn = j2 - P_;
                tgt2 = neg_t[b * N_ + jn]; valid2 = (jn < nl) ? 1.f : 0.f; pos2 = 0.f;
            }
        }
        const float4* e1 = (const float4*)(out_emb + (size_t)tgt1 * (3 * E_));
        const float4* e2 = (const float4*)(out_emb + (size_t)tgt2 * (3 * E_));
        float a1 = 0.f, a2 = 0.f;
#pragma unroll
        for (int i = 0; i < 6; i++) {
            const int k4 = lane + i * 32;
            const float4 c = ovs[k4];
            float4 r1 = e1[k4];
            a1 += r1.x * c.x + r1.y * c.y + r1.z * c.z + r1.w * c.w;
            if (have2) {
                float4 r2 = e2[k4];
                a2 += r2.x * c.x + r2.y * c.y + r2.z * c.z + r2.w * c.w;
            }
        }
#pragma unroll
        for (int o = 16; o; o >>= 1) {
            a1 += __shfl_xor_sync(0xffffffffu, a1, o);
            a2 += __shfl_xor_sync(0xffffffffu, a2, o);
        }
        if (lane == 0) {
            const int idx = b * NT_ + j;
            dout[idx]                = a1;
            dout[B_ * NT_ + idx]     = valid1;
            dout[2 * B_ * NT_ + idx] = pos1 * valid1;
            if (have2) {
                const int idx2 = b * NT_ + j2;
                dout[idx2]                = a2;
                dout[B_ * NT_ + idx2]     = valid2;
                dout[2 * B_ * NT_ + idx2] = pos2 * valid2;
            }
        }
    }
}

// ---------------------------------------------------------------------------
// Launch
// ---------------------------------------------------------------------------
extern "C" void kernel_launch(void* const* d_in, const int* in_sizes, int n_in,
                              void* d_out, int out_size) {
    const int*   attr           = (const int*)  d_in[0];
    const float* attr_tf        = (const float*)d_in[2];
    const float* attr_feat      = (const float*)d_in[3];
    const int*   attr_lens      = (const int*)  d_in[4];
    const int*   attr_lens_user = (const int*)  d_in[5];
    const int*   user_ids       = (const int*)  d_in[7];
    const int*   item_ids       = (const int*)  d_in[8];
    const int*   pos_targets    = (const int*)  d_in[9];
    const int*   pos_lens       = (const int*)  d_in[10];
    const int*   neg_targets    = (const int*)  d_in[11];
    const int*   neg_lens       = (const int*)  d_in[12];
    const float* attr_emb       = (const float*)d_in[13];
    const float* user_emb       = (const float*)d_in[14];
    const float* item_emb       = (const float*)d_in[15];
    const float* out_emb        = (const float*)d_in[16];
    const float* fw_W           = (const float*)d_in[17];
    const float* fw_b           = (const float*)d_in[18];
    const float* qkv_w          = (const float*)d_in[19];
    const float* qkv_b          = (const float*)d_in[20];
    const float* attn_out_w     = (const float*)d_in[21];
    const float* attn_out_b     = (const float*)d_in[22];
    const float* ln1_s          = (const float*)d_in[23];
    const float* ln1_b          = (const float*)d_in[24];
    const float* ff1_w          = (const float*)d_in[25];
    const float* ff1_b          = (const float*)d_in[26];
    const float* ff2_w          = (const float*)d_in[27];
    const float* ff2_b          = (const float*)d_in[28];
    const float* ln2_s          = (const float*)d_in[29];
    const float* ln2_b          = (const float*)d_in[30];

    float *x, *qkv, *attn, *ff;
    cudaGetSymbolAddress((void**)&x,    g_x);
    cudaGetSymbolAddress((void**)&qkv,  g_qkv);
    cudaGetSymbolAddress((void**)&attn, g_attn);
    cudaGetSymbolAddress((void**)&ff,   g_ff);

    const int gemm_smem = STAGES * 2 * TSZ * (int)sizeof(float);        // 61440
    cudaFuncSetAttribute(tgemm<false>, cudaFuncAttributeMaxDynamicSharedMemorySize,
                         gemm_smem);
    cudaFuncSetAttribute(tgemm<true>, cudaFuncAttributeMaxDynamicSharedMemorySize,
                         gemm_smem);
    const int ln_smem = STAGES * (ASZ2 + BSZ2) * (int)sizeof(float);    // 92160
    cudaFuncSetAttribute(tgemm_ln256, cudaFuncAttributeMaxDynamicSharedMemorySize,
                         ln_smem);
    const int attn_smem = ATTN_SMEMF * (int)sizeof(float);              // 105984
    cudaFuncSetAttribute(attn_kernel, cudaFuncAttributeMaxDynamicSharedMemorySize,
                         attn_smem);

    gather_kernel<<<(T_ * E_ / 4 + 255) / 256, 256>>>(attr, attr_emb, x);

    for (int l = 0; l < L_; l++) {
        const float* lqkv_w = qkv_w      + (size_t)l * 3 * E_ * E_;
        const float* lqkv_b = qkv_b      + (size_t)l * 3 * E_;
        const float* lao_w  = attn_out_w + (size_t)l * E_ * E_;
        const float* lao_b  = attn_out_b + (size_t)l * E_;
        const float* l1s    = ln1_s + (size_t)l * E_;
        const float* l1b    = ln1_b + (size_t)l * E_;
        const float* lf1_w  = ff1_w + (size_t)l * F_ * E_;
        const float* lf1_b  = ff1_b + (size_t)l * F_;
        const float* lf2_w  = ff2_w + (size_t)l * E_ * F_;
        const float* lf2_b  = ff2_b + (size_t)l * E_;
        const float* l2s    = ln2_s + (size_t)l * E_;
        const float* l2b    = ln2_b + (size_t)l * E_;

        tgemm<false><<<dim3(3 * E_ / 128, T_ / 128), 256, gemm_smem>>>(
            x, lqkv_w, lqkv_b, qkv, T_, 3 * E_, E_);
        attn_kernel<<<B_ * H_, 256, attn_smem>>>(qkv, attr_lens, attn);
        // x = LN(x + attn @ Wo^T + bo)
        tgemm_ln256<<<T_ / 128, 256, ln_smem>>>(
            attn, lao_w, lao_b, x, l1s, l1b, x, E_);
        tgemm<true><<<dim3(F_ / 128, T_ / 128), 256, gemm_smem>>>(
            x, lf1_w, lf1_b, ff, T_, F_, E_);
        // x = LN(x + ff @ W2^T + b2)
        tgemm_ln256<<<T_ / 128, 256, ln_smem>>>(
            ff, lf2_w, lf2_b, x, l2s, l2b, x, F_);
    }

    head_kernel<<<B_, 512>>>(x, attr_tf, attr_lens, attr_lens_user,
                             attr_feat, fw_W, fw_b,
                             user_ids, item_ids, user_emb, item_emb,
                             out_emb, pos_targets, pos_lens,
                             neg_targets, neg_lens, (float*)d_out);
}

// round 10
// speedup vs baseline: 1.0306x; 1.0306x over previous
#include <cuda_runtime.h>
#include <cuda_bf16.h>
#include <math.h>
#include <stdint.h>

// Problem constants
#define B_   256
#define S_   128
#define P_   100
#define N_   500
#define E_   256
#define H_   4
#define HD_  64
#define L_   2
#define F_   1024
#define T_   (B_ * S_)      // 32768 tokens
#define NT_  (P_ + N_)      // 600 targets
#define NTH_ (NT_ / 2)      // 300 pairs per sample

// ---------------------------------------------------------------------------
// Scratch (device globals — no allocation allowed)
// ---------------------------------------------------------------------------
__device__ float g_x   [(size_t)T_ * E_];
__device__ float g_qkv [(size_t)T_ * 3 * E_];
__device__ float g_attn[(size_t)T_ * E_];
__device__ float g_tmp [(size_t)T_ * E_];
__device__ float g_ff  [(size_t)T_ * F_];
__device__ float g_out [(size_t)B_ * 3 * E_];

// ---------------------------------------------------------------------------
// cp.async + tf32 helpers
// ---------------------------------------------------------------------------
__device__ __forceinline__ void cp16(void* sdst, const void* gsrc) {
    uint32_t s = (uint32_t)__cvta_generic_to_shared(sdst);
    asm volatile("cp.async.cg.shared.global [%0], [%1], 16;\n" :: "r"(s), "l"(gsrc));
}
__device__ __forceinline__ void cp_commit() {
    asm volatile("cp.async.commit_group;\n");
}
template<int NWait>
__device__ __forceinline__ void cp_wait() {
    asm volatile("cp.async.wait_group %0;\n" :: "n"(NWait));
}
__device__ __forceinline__ uint32_t f2tf32(float x) {
    uint32_t r;
    asm("cvt.rna.tf32.f32 %0, %1;" : "=r"(r) : "f"(x));
    return r;
}
#define MMA_TF32(d, a, b)                                                     \
    asm volatile(                                                             \
        "mma.sync.aligned.m16n8k8.row.col.f32.tf32.tf32.f32 "                 \
        "{%0,%1,%2,%3}, {%4,%5,%6,%7}, {%8,%9}, {%0,%1,%2,%3};"               \
        : "+f"(d[0]), "+f"(d[1]), "+f"(d[2]), "+f"(d[3])                      \
        : "r"(a[0]), "r"(a[1]), "r"(a[2]), "r"(a[3]), "r"(b[0]), "r"(b[1]))

// ---------------------------------------------------------------------------
// Embedding gather (float4)
// ---------------------------------------------------------------------------
__global__ void gather_kernel(const int* __restrict__ attr,
                              const float* __restrict__ emb,
                              float* __restrict__ x) {
    int i4 = blockIdx.x * blockDim.x + threadIdx.x;
    if (i4 < T_ * (E_ / 4)) {
        int t = i4 >> 6;
        int e4 = i4 & 63;
        ((float4*)x)[i4] = ((const float4*)emb)[(size_t)attr[t] * (E_ / 4) + e4];
    }
}

// ---------------------------------------------------------------------------
// TF32 GEMM: C = A @ B^T + bias (opt ReLU). Block 128x128, BK=16, 8 warps
// of 64x32, 3-stage cp.async, 2 CTAs/SM.  (R6/R8-proven)
// ---------------------------------------------------------------------------
#define LDA    20
#define TSZ    (128 * LDA)
#define STAGES 3

template<bool RELU>
__global__ __launch_bounds__(256, 2)
void tgemm(const float* __restrict__ A, const float* __restrict__ Bm,
           const float* __restrict__ bias, float* __restrict__ C,
           int M, int N, int K) {
    extern __shared__ float smw[];
    float* As = smw;
    float* Bs = smw + STAGES * TSZ;

    const int bm   = blockIdx.y * 128;
    const int bn   = blockIdx.x * 128;
    const int t    = threadIdx.x;
    const int lane = t & 31;
    const int wid  = t >> 5;
    const int wm   = (wid & 1) * 64;
    const int wn   = (wid >> 1) * 32;
    const int g    = lane >> 2;
    const int tg   = lane & 3;

    const int lrow = t >> 1;
    const int lkb  = (t & 1) * 8;
    const float* Ap = A  + (size_t)(bm + lrow) * K + lkb;
    const float* Bp = Bm + (size_t)(bn + lrow) * K + lkb;

    float acc[4][4][4];
#pragma unroll
    for (int i = 0; i < 4; i++)
#pragma unroll
        for (int j = 0; j < 4; j++)
#pragma unroll
            for (int r = 0; r < 4; r++) acc[i][j][r] = 0.f;

    const int nk = K >> 4;
#pragma unroll
    for (int s = 0; s < STAGES - 1; s++) {
        const int k0 = s << 4;
        cp16(&As[s * TSZ + lrow * LDA + lkb],     Ap + k0);
        cp16(&As[s * TSZ + lrow * LDA + lkb + 4], Ap + k0 + 4);
        cp16(&Bs[s * TSZ + lrow * LDA + lkb],     Bp + k0);
        cp16(&Bs[s * TSZ + lrow * LDA + lkb + 4], Bp + k0 + 4);
        cp_commit();
    }

    int cur = 0;
    for (int kt = 0; kt < nk; kt++) {
        if (kt < nk - 1) cp_wait<STAGES - 2>(); else cp_wait<0>();
        __syncthreads();

        const float* Ac = As + cur * TSZ;
        const float* Bc = Bs + cur * TSZ;
#pragma unroll
        for (int ks = 0; ks < 2; ks++) {
            const int k0 = ks * 8;
            uint32_t af[4][4], bf[4][2];
#pragma unroll
            for (int mf = 0; mf < 4; mf++) {
                const int row = wm + mf * 16 + g;
                af[mf][0] = f2tf32(Ac[row * LDA + k0 + tg]);
                af[mf][1] = f2tf32(Ac[(row + 8) * LDA + k0 + tg]);
                af[mf][2] = f2tf32(Ac[row * LDA + k0 + tg + 4]);
                af[mf][3] = f2tf32(Ac[(row + 8) * LDA + k0 + tg + 4]);
            }
#pragma unroll
            for (int nf = 0; nf < 4; nf++) {
                const int col = wn + nf * 8 + g;
                bf[nf][0] = f2tf32(Bc[col * LDA + k0 + tg]);
                bf[nf][1] = f2tf32(Bc[col * LDA + k0 + tg + 4]);
            }
#pragma unroll
            for (int mf = 0; mf < 4; mf++)
#pragma unroll
                for (int nf = 0; nf < 4; nf++) MMA_TF32(acc[mf][nf], af[mf], bf[nf]);
        }

        const int pf = kt + STAGES - 1;
        if (pf < nk) {
            const int ps = pf % STAGES;
            const int k0 = pf << 4;
            cp16(&As[ps * TSZ + lrow * LDA + lkb],     Ap + k0);
            cp16(&As[ps * TSZ + lrow * LDA + lkb + 4], Ap + k0 + 4);
            cp16(&Bs[ps * TSZ + lrow * LDA + lkb],     Bp + k0);
            cp16(&Bs[ps * TSZ + lrow * LDA + lkb + 4], Bp + k0 + 4);
            cp_commit();
        }
        cur = (cur + 1 == STAGES) ? 0 : cur + 1;
    }

#pragma unroll
    for (int nf = 0; nf < 4; nf++) {
        const int col = bn + wn + nf * 8 + 2 * tg;
        const float b0v = bias[col], b1v = bias[col + 1];
#pragma unroll
        for (int mf = 0; mf < 4; mf++) {
            const int row = bm + wm + mf * 16 + g;
            float v0 = acc[mf][nf][0] + b0v;
            float v1 = acc[mf][nf][1] + b1v;
            float v2 = acc[mf][nf][2] + b0v;
            float v3 = acc[mf][nf][3] + b1v;
            if (RELU) {
                v0 = fmaxf(v0, 0.f); v1 = fmaxf(v1, 0.f);
                v2 = fmaxf(v2, 0.f); v3 = fmaxf(v3, 0.f);
            }
            *(float2*)(C + (size_t)row * N + col)       = make_float2(v0, v1);
            *(float2*)(C + (size_t)(row + 8) * N + col) = make_float2(v2, v3);
        }
    }
}

// ---------------------------------------------------------------------------
// Tensor-core attention (R8-proven): one block per (b,h), 256 threads.
// ---------------------------------------------------------------------------
#define QLD 68
#define PLD2 132
#define VT_OFF 0
#define Q_OFF  (64 * PLD2)
#define K_OFF  (Q_OFF + 128 * QLD)
#define P_OFF  Q_OFF
#define PART_OFF (K_OFF + 128 * QLD)
#define RSUM_OFF (PART_OFF + 512)
#define ATTN_SMEMF (RSUM_OFF + 128)

__global__ __launch_bounds__(256)
void attn_kernel(const float* __restrict__ qkv,
                 const int* __restrict__ lens,
                 float* __restrict__ out) {
    const int bh = blockIdx.x;
    const int b  = bh / H_;
    const int h  = bh % H_;
    extern __shared__ float sm[];

    const int t    = threadIdx.x;
    const int lane = t & 31;
    const int wid  = t >> 5;
    const int g    = lane >> 2;
    const int tg   = lane & 3;
    const int len  = lens[b];

    for (int i4 = t; i4 < S_ * HD_ / 4; i4 += 256) {
        const int s  = i4 >> 4;
        const int d4 = i4 & 15;
        const float4* base =
            (const float4*)(qkv + (size_t)(b * S_ + s) * (3 * E_) + h * HD_);
        float4 qv = base[d4];
        float4 kv = base[(E_ / 4) + d4];
        float4 vv = base[(2 * E_ / 4) + d4];
        *(float4*)&sm[Q_OFF + s * QLD + d4 * 4] = qv;
        *(float4*)&sm[K_OFF + s * QLD + d4 * 4] = kv;
        const int d0 = d4 * 4;
        sm[VT_OFF + (d0 + 0) * PLD2 + s] = vv.x;
        sm[VT_OFF + (d0 + 1) * PLD2 + s] = vv.y;
        sm[VT_OFF + (d0 + 2) * PLD2 + s] = vv.z;
        sm[VT_OFF + (d0 + 3) * PLD2 + s] = vv.w;
    }
    __syncthreads();

    const int wm = (wid & 1) * 64;
    const int wn = (wid >> 1) * 32;
    float acc[4][4][4];
#pragma unroll
    for (int i = 0; i < 4; i++)
#pragma unroll
        for (int j = 0; j < 4; j++)
#pragma unroll
            for (int r = 0; r < 4; r++) acc[i][j][r] = 0.f;

#pragma unroll
    for (int ks = 0; ks < 8; ks++) {
        const int k0 = ks * 8;
        uint32_t af[4][4], bf[4][2];
#pragma unroll
        for (int mf = 0; mf < 4; mf++) {
            const int row = wm + mf * 16 + g;
            af[mf][0] = f2tf32(sm[Q_OFF + row * QLD + k0 + tg]);
            af[mf][1] = f2tf32(sm[Q_OFF + (row + 8) * QLD + k0 + tg]);
            af[mf][2] = f2tf32(sm[Q_OFF + row * QLD + k0 + tg + 4]);
            af[mf][3] = f2tf32(sm[Q_OFF + (row + 8) * QLD + k0 + tg + 4]);
        }
#pragma unroll
        for (int nf = 0; nf < 4; nf++) {
            const int col = wn + nf * 8 + g;
            bf[nf][0] = f2tf32(sm[K_OFF + col * QLD + k0 + tg]);
            bf[nf][1] = f2tf32(sm[K_OFF + col * QLD + k0 + tg + 4]);
        }
#pragma unroll
        for (int mf = 0; mf < 4; mf++)
#pragma unroll
            for (int nf = 0; nf < 4; nf++) MMA_TF32(acc[mf][nf], af[mf], bf[nf]);
    }

    float rs[4][2];
#pragma unroll
    for (int mf = 0; mf < 4; mf++) { rs[mf][0] = 0.f; rs[mf][1] = 0.f; }
#pragma unroll
    for (int mf = 0; mf < 4; mf++) {
#pragma unroll
        for (int nf = 0; nf < 4; nf++) {
            const int c0 = wn + nf * 8 + 2 * tg;
            const int c1 = c0 + 1;
            float* d = acc[mf][nf];
            d[0] = (c0 < len) ? __expf(d[0] * 0.125f) : 0.f;
            d[1] = (c1 < len) ? __expf(d[1] * 0.125f) : 0.f;
            d[2] = (c0 < len) ? __expf(d[2] * 0.125f) : 0.f;
            d[3] = (c1 < len) ? __expf(d[3] * 0.125f) : 0.f;
            rs[mf][0] += d[0] + d[1];
            rs[mf][1] += d[2] + d[3];
        }
#pragma unroll
        for (int o = 1; o < 4; o <<= 1) {
            rs[mf][0] += __shfl_xor_sync(0xffffffffu, rs[mf][0], o);
            rs[mf][1] += __shfl_xor_sync(0xffffffffu, rs[mf][1], o);
        }
    }
    __syncthreads();

    const int nidx = wid >> 1;
#pragma unroll
    for (int mf = 0; mf < 4; mf++) {
        const int r0 = wm + mf * 16 + g;
        const int r1 = r0 + 8;
#pragma unroll
        for (int nf = 0; nf < 4; nf++) {
            const int c0 = wn + nf * 8 + 2 * tg;
            const float* d = acc[mf][nf];
            *(float2*)&sm[P_OFF + r0 * PLD2 + c0] = make_float2(d[0], d[1]);
            *(float2*)&sm[P_OFF + r1 * PLD2 + c0] = make_float2(d[2], d[3]);
        }
        if (tg == 0) {
            sm[PART_OFF + r0 * 4 + nidx] = rs[mf][0];
            sm[PART_OFF + r1 * 4 + nidx] = rs[mf][1];
        }
    }
    __syncthreads();

    if (t < 128) {
        const float s = sm[PART_OFF + t * 4] + sm[PART_OFF + t * 4 + 1] +
                        sm[PART_OFF + t * 4 + 2] + sm[PART_OFF + t * 4 + 3];
        sm[RSUM_OFF + t] = 1.f / s;
    }
    __syncthreads();

    const int wm2 = (wid & 3) * 32;
    const int wn2 = (wid >> 2) * 32;
    float acc2[2][4][4];
#pragma unroll
    for (int i = 0; i < 2; i++)
#pragma unroll
        for (int j = 0; j < 4; j++)
#pragma unroll
            for (int r = 0; r < 4; r++) acc2[i][j][r] = 0.f;

#pragma unroll
    for (int ks = 0; ks < 16; ks++) {
        const int k0 = ks * 8;
        uint32_t af[2][4], bf[4][2];
#pragma unroll
        for (int mf = 0; mf < 2; mf++) {
            const int row = wm2 + mf * 16 + g;
            af[mf][0] = f2tf32(sm[P_OFF + row * PLD2 + k0 + tg]);
            af[mf][1] = f2tf32(sm[P_OFF + (row + 8) * PLD2 + k0 + tg]);
            af[mf][2] = f2tf32(sm[P_OFF + row * PLD2 + k0 + tg + 4]);
            af[mf][3] = f2tf32(sm[P_OFF + (row + 8) * PLD2 + k0 + tg + 4]);
        }
#pragma unroll
        for (int nf = 0; nf < 4; nf++) {
            const int col = wn2 + nf * 8 + g;
            bf[nf][0] = f2tf32(sm[VT_OFF + col * PLD2 + k0 + tg]);
            bf[nf][1] = f2tf32(sm[VT_OFF + col * PLD2 + k0 + tg + 4]);
        }
#pragma unroll
        for (int mf = 0; mf < 2; mf++)
#pragma unroll
            for (int nf = 0; nf < 4; nf++) MMA_TF32(acc2[mf][nf], af[mf], bf[nf]);
    }

#pragma unroll
    for (int mf = 0; mf < 2; mf++) {
        const int r0 = wm2 + mf * 16 + g;
        const int r1 = r0 + 8;
        const float i0 = sm[RSUM_OFF + r0];
        const float i1 = sm[RSUM_OFF + r1];
#pragma unroll
        for (int nf = 0; nf < 4; nf++) {
            const int c = wn2 + nf * 8 + 2 * tg;
            const float* d = acc2[mf][nf];
            *(float2*)(out + (size_t)(b * S_ + r0) * E_ + h * HD_ + c) =
                make_float2(d[0] * i0, d[1] * i0);
            *(float2*)(out + (size_t)(b * S_ + r1) * E_ + h * HD_ + c) =
                make_float2(d[2] * i1, d[3] * i1);
        }
    }
}

// ---------------------------------------------------------------------------
// Fused residual add + LayerNorm: warp per token, 8 tokens per block
// ---------------------------------------------------------------------------
__global__ __launch_bounds__(256)
void add_ln_kernel(const float* __restrict__ x, const float* __restrict__ y,
                   const float* __restrict__ sc, const float* __restrict__ bi,
                   float* __restrict__ out) {
    const int tok  = blockIdx.x * 8 + (threadIdx.x >> 5);
    const int lane = threadIdx.x & 31;
    const size_t base4 = (size_t)tok * (E_ / 4);

    float4 v0 = ((const float4*)x)[base4 + lane];
    float4 v1 = ((const float4*)x)[base4 + 32 + lane];
    float4 y0 = ((const float4*)y)[base4 + lane];
    float4 y1 = ((const float4*)y)[base4 + 32 + lane];
    v0.x += y0.x; v0.y += y0.y; v0.z += y0.z; v0.w += y0.w;
    v1.x += y1.x; v1.y += y1.y; v1.z += y1.z; v1.w += y1.w;

    float s = v0.x + v0.y + v0.z + v0.w + v1.x + v1.y + v1.z + v1.w;
#pragma unroll
    for (int o = 16; o; o >>= 1) s += __shfl_xor_sync(0xffffffffu, s, o);
    const float m = s * (1.f / E_);

    float q =
        (v0.x - m) * (v0.x - m) + (v0.y - m) * (v0.y - m) +
        (v0.z - m) * (v0.z - m) + (v0.w - m) * (v0.w - m) +
        (v1.x - m) * (v1.x - m) + (v1.y - m) * (v1.y - m) +
        (v1.z - m) * (v1.z - m) + (v1.w - m) * (v1.w - m);
#pragma unroll
    for (int o = 16; o; o >>= 1) q += __shfl_xor_sync(0xffffffffu, q, o);
    const float rstd = rsqrtf(q * (1.f / E_) + 1e-5f);

    const float4 s0 = ((const float4*)sc)[lane];
    const float4 s1 = ((const float4*)sc)[32 + lane];
    const float4 b0 = ((const float4*)bi)[lane];
    const float4 b1 = ((const float4*)bi)[32 + lane];
    float4 o0, o1;
    o0.x = (v0.x - m) * rstd * s0.x + b0.x;
    o0.y = (v0.y - m) * rstd * s0.y + b0.y;
    o0.z = (v0.z - m) * rstd * s0.z + b0.z;
    o0.w = (v0.w - m) * rstd * s0.w + b0.w;
    o1.x = (v1.x - m) * rstd * s1.x + b1.x;
    o1.y = (v1.y - m) * rstd * s1.y + b1.y;
    o1.z = (v1.z - m) * rstd * s1.z + b1.z;
    o1.w = (v1.w - m) * rstd * s1.w + b1.w;
    ((float4*)out)[base4 + lane]      = o0;
    ((float4*)out)[base4 + 32 + lane] = o1;
}

// ---------------------------------------------------------------------------
// Weighted pool + concat (+ per-sample sigmoid gate computed in-block)
// ---------------------------------------------------------------------------
__global__ __launch_bounds__(256)
void pool_kernel(const float* __restrict__ x, const float* __restrict__ attr_tf,
                 const int* __restrict__ lens, const int* __restrict__ lens_user,
                 const float* __restrict__ feat, const float* __restrict__ fW,
                 const float* __restrict__ fb,
                 const int* __restrict__ user_ids, const int* __restrict__ item_ids,
                 const float* __restrict__ user_emb, const float* __restrict__ item_emb,
                 float* __restrict__ out) {
    const int b = blockIdx.x;
    const int e = threadIdx.x;
    __shared__ float w[S_];
    __shared__ float wu_s;
    if (e == 0) {
        float z = fb[0];
#pragma unroll
        for (int i = 0; i < 13; i++) z += feat[b * 13 + i] * fW[i];
        wu_s = 1.f / (1.f + expf(-z));
    }
    __syncthreads();
    if (e < S_) {
        const int s = e;
        float wgt = 0.f;
        if (s < lens[b]) {
            const float g = (s < lens_user[b]) ? wu_s : (1.f - wu_s);
            wgt = attr_tf[b * S_ + s] * g;
        }
        w[s] = wgt;
    }
    __syncthreads();
    float acc = 0.f;
    const float* xb = x + (size_t)b * S_ * E_ + e;
    for (int s = 0; s < S_; s++) acc += w[s] * xb[(size_t)s * E_];
    out[(size_t)b * 3 * E_ + E_ + e]     = acc;
    out[(size_t)b * 3 * E_ + e]          = user_emb[(size_t)user_ids[b] * E_ + e];
    out[(size_t)b * 3 * E_ + 2 * E_ + e] = item_emb[(size_t)item_ids[b] * E_ + e];
}

// ---------------------------------------------------------------------------
// Scoring head v3: one warp per PAIR of targets (j, j+300). 76800 warps /
// 9600 blocks -> full-chip MLP on the out_emb gather, no wave tail.
// outv reads come from global (768KB -> L2/L1 resident).
// ---------------------------------------------------------------------------
__global__ __launch_bounds__(256)
void logits_kernel(const float* __restrict__ outv, const float* __restrict__ out_emb,
                   const int* __restrict__ pos_t, const int* __restrict__ pos_l,
                   const int* __restrict__ neg_t, const int* __restrict__ neg_l,
                   float* __restrict__ dout) {
    const int gw   = (int)((blockIdx.x * blockDim.x + threadIdx.x) >> 5);
    const int lane = threadIdx.x & 31;
    if (gw >= B_ * NTH_) return;
    const int b  = gw / NTH_;
    const int j1 = gw % NTH_;
    const int j2 = j1 + NTH_;

    const int pl = pos_l[b];
    const int nl = neg_l[b];

    int tgt1; float valid1, posf1;
    if (j1 < P_) {
        tgt1 = pos_t[b * P_ + j1]; valid1 = (j1 < pl) ? 1.f : 0.f; posf1 = 1.f;
    } else {
        const int jn = j1 - P_;
        tgt1 = neg_t[b * N_ + jn]; valid1 = (jn < nl) ? 1.f : 0.f; posf1 = 0.f;
    }
    int tgt2; float valid2, posf2;
    {
        const int jn = j2 - P_;    // j2 >= 300 > P_ always
        tgt2 = neg_t[b * N_ + jn]; valid2 = (jn < nl) ? 1.f : 0.f; posf2 = 0.f;
    }

    const float4* ovs = (const float4*)(outv + (size_t)b * (3 * E_));
    const float4* e1  = (const float4*)(out_emb + (size_t)tgt1 * (3 * E_));
    const float4* e2  = (const float4*)(out_emb + (size_t)tgt2 * (3 * E_));
    float a1 = 0.f, a2 = 0.f;
#pragma unroll
    for (int i = 0; i < 6; i++) {
        const int k4 = lane + i * 32;
        const float4 c  = ovs[k4];
        const float4 r1 = e1[k4];
        const float4 r2 = e2[k4];
        a1 += r1.x * c.x + r1.y * c.y + r1.z * c.z + r1.w * c.w;
        a2 += r2.x * c.x + r2.y * c.y + r2.z * c.z + r2.w * c.w;
    }
#pragma unroll
    for (int o = 16; o; o >>= 1) {
        a1 += __shfl_xor_sync(0xffffffffu, a1, o);
        a2 += __shfl_xor_sync(0xffffffffu, a2, o);
    }
    if (lane == 0) {
        const int idx1 = b * NT_ + j1;
        const int idx2 = b * NT_ + j2;
        dout[idx1]                = a1;
        dout[B_ * NT_ + idx1]     = valid1;
        dout[2 * B_ * NT_ + idx1] = posf1 * valid1;
        dout[idx2]                = a2;
        dout[B_ * NT_ + idx2]     = valid2;
        dout[2 * B_ * NT_ + idx2] = posf2 * valid2;
    }
}

// ---------------------------------------------------------------------------
// Launch
// ---------------------------------------------------------------------------
extern "C" void kernel_launch(void* const* d_in, const int* in_sizes, int n_in,
                              void* d_out, int out_size) {
    const int*   attr           = (const int*)  d_in[0];
    const float* attr_tf        = (const float*)d_in[2];
    const float* attr_feat      = (const float*)d_in[3];
    const int*   attr_lens      = (const int*)  d_in[4];
    const int*   attr_lens_user = (const int*)  d_in[5];
    const int*   user_ids       = (const int*)  d_in[7];
    const int*   item_ids       = (const int*)  d_in[8];
    const int*   pos_targets    = (const int*)  d_in[9];
    const int*   pos_lens       = (const int*)  d_in[10];
    const int*   neg_targets    = (const int*)  d_in[11];
    const int*   neg_lens       = (const int*)  d_in[12];
    const float* attr_emb       = (const float*)d_in[13];
    const float* user_emb       = (const float*)d_in[14];
    const float* item_emb       = (const float*)d_in[15];
    const float* out_emb        = (const float*)d_in[16];
    const float* fw_W           = (const float*)d_in[17];
    const float* fw_b           = (const float*)d_in[18];
    const float* qkv_w          = (const float*)d_in[19];
    const float* qkv_b          = (const float*)d_in[20];
    const float* attn_out_w     = (const float*)d_in[21];
    const float* attn_out_b     = (const float*)d_in[22];
    const float* ln1_s          = (const float*)d_in[23];
    const float* ln1_b          = (const float*)d_in[24];
    const float* ff1_w          = (const float*)d_in[25];
    const float* ff1_b          = (const float*)d_in[26];
    const float* ff2_w          = (const float*)d_in[27];
    const float* ff2_b          = (const float*)d_in[28];
    const float* ln2_s          = (const float*)d_in[29];
    const float* ln2_b          = (const float*)d_in[30];

    float *x, *qkv, *attn, *tmp, *ff, *outv;
    cudaGetSymbolAddress((void**)&x,    g_x);
    cudaGetSymbolAddress((void**)&qkv,  g_qkv);
    cudaGetSymbolAddress((void**)&attn, g_attn);
    cudaGetSymbolAddress((void**)&tmp,  g_tmp);
    cudaGetSymbolAddress((void**)&ff,   g_ff);
    cudaGetSymbolAddress((void**)&outv, g_out);

    const int gemm_smem = STAGES * 2 * TSZ * (int)sizeof(float);   // 61440
    cudaFuncSetAttribute(tgemm<false>, cudaFuncAttributeMaxDynamicSharedMemorySize,
                         gemm_smem);
    cudaFuncSetAttribute(tgemm<true>, cudaFuncAttributeMaxDynamicSharedMemorySize,
                         gemm_smem);
    const int attn_smem = ATTN_SMEMF * (int)sizeof(float);         // 105984
    cudaFuncSetAttribute(attn_kernel, cudaFuncAttributeMaxDynamicSharedMemorySize,
                         attn_smem);

    gather_kernel<<<(T_ * E_ / 4 + 255) / 256, 256>>>(attr, attr_emb, x);

    for (int l = 0; l < L_; l++) {
        const float* lqkv_w = qkv_w      + (size_t)l * 3 * E_ * E_;
        const float* lqkv_b = qkv_b      + (size_t)l * 3 * E_;
        const float* lao_w  = attn_out_w + (size_t)l * E_ * E_;
        const float* lao_b  = attn_out_b + (size_t)l * E_;
        const float* l1s    = ln1_s + (size_t)l * E_;
        const float* l1b    = ln1_b + (size_t)l * E_;
        const float* lf1_w  = ff1_w + (size_t)l * F_ * E_;
        const float* lf1_b  = ff1_b + (size_t)l * F_;
        const float* lf2_w  = ff2_w + (size_t)l * E_ * F_;
        const float* lf2_b  = ff2_b + (size_t)l * E_;
        const float* l2s    = ln2_s + (size_t)l * E_;
        const float* l2b    = ln2_b + (size_t)l * E_;

        tgemm<false><<<dim3(3 * E_ / 128, T_ / 128), 256, gemm_smem>>>(
            x, lqkv_w, lqkv_b, qkv, T_, 3 * E_, E_);
        attn_kernel<<<B_ * H_, 256, attn_smem>>>(qkv, attr_lens, attn);
        tgemm<false><<<dim3(E_ / 128, T_ / 128), 256, gemm_smem>>>(
            attn, lao_w, lao_b, tmp, T_, E_, E_);
        add_ln_kernel<<<T_ / 8, 256>>>(x, tmp, l1s, l1b, x);
        tgemm<true><<<dim3(F_ / 128, T_ / 128), 256, gemm_smem>>>(
            x, lf1_w, lf1_b, ff, T_, F_, E_);
        tgemm<false><<<dim3(E_ / 128, T_ / 128), 256, gemm_smem>>>(
            ff, lf2_w, lf2_b, tmp, T_, E_, F_);
        add_ln_kernel<<<T_ / 8, 256>>>(x, tmp, l2s, l2b, x);
    }

    pool_kernel<<<B_, 256>>>(x, attr_tf, attr_lens, attr_lens_user,
                             attr_feat, fw_W, fw_b,
                             user_ids, item_ids, user_emb, item_emb, outv);

    const int nwarps = B_ * NTH_;                      // 76800
    logits_kernel<<<(nwarps * 32 + 255) / 256, 256>>>(
        outv, out_emb, pos_targets, pos_lens, neg_targets, neg_lens,
        (float*)d_out);
}

// round 11
// speedup vs baseline: 1.0753x; 1.0434x over previous
#include <cuda_runtime.h>
#include <cuda_bf16.h>
#include <math.h>
#include <stdint.h>

// Problem constants
#define B_   256
#define S_   128
#define P_   100
#define N_   500
#define E_   256
#define H_   4
#define HD_  64
#define L_   2
#define F_   1024
#define T_   (B_ * S_)      // 32768 tokens
#define NT_  (P_ + N_)      // 600 targets
#define NTH_ (NT_ / 2)      // 300 pairs per sample

// ---------------------------------------------------------------------------
// Scratch (device globals — no allocation allowed)
// ---------------------------------------------------------------------------
__device__ float g_x   [(size_t)T_ * E_];
__device__ float g_qkv [(size_t)T_ * 3 * E_];
__device__ float g_attn[(size_t)T_ * E_];
__device__ float g_tmp [(size_t)T_ * E_];
__device__ float g_ff  [(size_t)T_ * F_];
__device__ float g_out [(size_t)B_ * 3 * E_];
__device__ float g_wr  [1572864];             // tf32-rounded weights (6MB)

// float offsets into g_wr
#define WR_QKV 0
#define WR_AO  393216
#define WR_FF1 524288
#define WR_FF2 1048576

// ---------------------------------------------------------------------------
// cp.async + tf32 helpers
// ---------------------------------------------------------------------------
__device__ __forceinline__ void cp16(void* sdst, const void* gsrc) {
    uint32_t s = (uint32_t)__cvta_generic_to_shared(sdst);
    asm volatile("cp.async.cg.shared.global [%0], [%1], 16;\n" :: "r"(s), "l"(gsrc));
}
__device__ __forceinline__ void cp_commit() {
    asm volatile("cp.async.commit_group;\n");
}
template<int NWait>
__device__ __forceinline__ void cp_wait() {
    asm volatile("cp.async.wait_group %0;\n" :: "n"(NWait));
}
// round-to-nearest tf32, returned as float bits (mantissa bits 12..0 zero)
__device__ __forceinline__ float rndf(float x) {
    uint32_t r;
    asm("cvt.rna.tf32.f32 %0, %1;" : "=r"(r) : "f"(x));
    return __uint_as_float(r);
}
#define MMA_TF32(d, a, b)                                                     \
    asm volatile(                                                             \
        "mma.sync.aligned.m16n8k8.row.col.f32.tf32.tf32.f32 "                 \
        "{%0,%1,%2,%3}, {%4,%5,%6,%7}, {%8,%9}, {%0,%1,%2,%3};"               \
        : "+f"(d[0]), "+f"(d[1]), "+f"(d[2]), "+f"(d[3])                      \
        : "r"(a[0]), "r"(a[1]), "r"(a[2]), "r"(a[3]), "r"(b[0]), "r"(b[1]))

// ---------------------------------------------------------------------------
// Weight pre-rounding: all 4 weight tensors -> g_wr (tf32-rounded).
// 393216 float4 total: qkv 98304 | ao 32768 | ff1 131072 | ff2 131072.
// ---------------------------------------------------------------------------
__global__ void round_w_kernel(const float4* __restrict__ qkvw,
                               const float4* __restrict__ aow,
                               const float4* __restrict__ f1w,
                               const float4* __restrict__ f2w,
                               float4* __restrict__ dst) {
    const int i = blockIdx.x * blockDim.x + threadIdx.x;
    if (i >= 393216) return;
    float4 v;
    int o = i;
    if (o < 98304)               v = qkvw[o];
    else if ((o -= 98304) < 32768)  v = aow[o];
    else if ((o -= 32768) < 131072) v = f1w[o];
    else                          v = f2w[o - 131072];
    v.x = rndf(v.x); v.y = rndf(v.y); v.z = rndf(v.z); v.w = rndf(v.w);
    dst[i] = v;
}

// ---------------------------------------------------------------------------
// Embedding gather (float4), output rounded to tf32
// ---------------------------------------------------------------------------
__global__ void gather_kernel(const int* __restrict__ attr,
                              const float* __restrict__ emb,
                              float* __restrict__ x) {
    int i4 = blockIdx.x * blockDim.x + threadIdx.x;
    if (i4 < T_ * (E_ / 4)) {
        int t = i4 >> 6;
        int e4 = i4 & 63;
        float4 v = ((const float4*)emb)[(size_t)attr[t] * (E_ / 4) + e4];
        v.x = rndf(v.x); v.y = rndf(v.y); v.z = rndf(v.z); v.w = rndf(v.w);
        ((float4*)x)[i4] = v;
    }
}

// ---------------------------------------------------------------------------
// TF32 GEMM: C = A @ B^T + bias (opt ReLU, opt tf32-round of C).
// Inputs A, B are PRE-ROUNDED to tf32 -> no cvt in the inner loop.
// Block 128x128, BK=16, 8 warps of 64x32, 3-stage cp.async, 2 CTAs/SM.
// ---------------------------------------------------------------------------
#define LDA    20
#define TSZ    (128 * LDA)
#define STAGES 3

template<bool RELU, bool ROUND>
__global__ __launch_bounds__(256, 2)
void tgemm(const float* __restrict__ A, const float* __restrict__ Bm,
           const float* __restrict__ bias, float* __restrict__ C,
           int M, int N, int K) {
    extern __shared__ float smw[];
    float* As = smw;
    float* Bs = smw + STAGES * TSZ;

    const int bm   = blockIdx.y * 128;
    const int bn   = blockIdx.x * 128;
    const int t    = threadIdx.x;
    const int lane = t & 31;
    const int wid  = t >> 5;
    const int wm   = (wid & 1) * 64;
    const int wn   = (wid >> 1) * 32;
    const int g    = lane >> 2;
    const int tg   = lane & 3;

    const int lrow = t >> 1;
    const int lkb  = (t & 1) * 8;
    const float* Ap = A  + (size_t)(bm + lrow) * K + lkb;
    const float* Bp = Bm + (size_t)(bn + lrow) * K + lkb;

    float acc[4][4][4];
#pragma unroll
    for (int i = 0; i < 4; i++)
#pragma unroll
        for (int j = 0; j < 4; j++)
#pragma unroll
            for (int r = 0; r < 4; r++) acc[i][j][r] = 0.f;

    const int nk = K >> 4;
#pragma unroll
    for (int s = 0; s < STAGES - 1; s++) {
        const int k0 = s << 4;
        cp16(&As[s * TSZ + lrow * LDA + lkb],     Ap + k0);
        cp16(&As[s * TSZ + lrow * LDA + lkb + 4], Ap + k0 + 4);
        cp16(&Bs[s * TSZ + lrow * LDA + lkb],     Bp + k0);
        cp16(&Bs[s * TSZ + lrow * LDA + lkb + 4], Bp + k0 + 4);
        cp_commit();
    }

    int cur = 0;
    for (int kt = 0; kt < nk; kt++) {
        if (kt < nk - 1) cp_wait<STAGES - 2>(); else cp_wait<0>();
        __syncthreads();

        const uint32_t* Ac = (const uint32_t*)(As + cur * TSZ);
        const uint32_t* Bc = (const uint32_t*)(Bs + cur * TSZ);
#pragma unroll
        for (int ks = 0; ks < 2; ks++) {
            const int k0 = ks * 8;
            uint32_t af[4][4], bf[4][2];
#pragma unroll
            for (int mf = 0; mf < 4; mf++) {
                const int row = wm + mf * 16 + g;
                af[mf][0] = Ac[row * LDA + k0 + tg];
                af[mf][1] = Ac[(row + 8) * LDA + k0 + tg];
                af[mf][2] = Ac[row * LDA + k0 + tg + 4];
                af[mf][3] = Ac[(row + 8) * LDA + k0 + tg + 4];
            }
#pragma unroll
            for (int nf = 0; nf < 4; nf++) {
                const int col = wn + nf * 8 + g;
                bf[nf][0] = Bc[col * LDA + k0 + tg];
                bf[nf][1] = Bc[col * LDA + k0 + tg + 4];
            }
#pragma unroll
            for (int mf = 0; mf < 4; mf++)
#pragma unroll
                for (int nf = 0; nf < 4; nf++) MMA_TF32(acc[mf][nf], af[mf], bf[nf]);
        }

        const int pf = kt + STAGES - 1;
        if (pf < nk) {
            const int ps = pf % STAGES;
            const int k0 = pf << 4;
            cp16(&As[ps * TSZ + lrow * LDA + lkb],     Ap + k0);
            cp16(&As[ps * TSZ + lrow * LDA + lkb + 4], Ap + k0 + 4);
            cp16(&Bs[ps * TSZ + lrow * LDA + lkb],     Bp + k0);
            cp16(&Bs[ps * TSZ + lrow * LDA + lkb + 4], Bp + k0 + 4);
            cp_commit();
        }
        cur = (cur + 1 == STAGES) ? 0 : cur + 1;
    }

#pragma unroll
    for (int nf = 0; nf < 4; nf++) {
        const int col = bn + wn + nf * 8 + 2 * tg;
        const float b0v = bias[col], b1v = bias[col + 1];
#pragma unroll
        for (int mf = 0; mf < 4; mf++) {
            const int row = bm + wm + mf * 16 + g;
            float v0 = acc[mf][nf][0] + b0v;
            float v1 = acc[mf][nf][1] + b1v;
            float v2 = acc[mf][nf][2] + b0v;
            float v3 = acc[mf][nf][3] + b1v;
            if (RELU) {
                v0 = fmaxf(v0, 0.f); v1 = fmaxf(v1, 0.f);
                v2 = fmaxf(v2, 0.f); v3 = fmaxf(v3, 0.f);
            }
            if (ROUND) {
                v0 = rndf(v0); v1 = rndf(v1); v2 = rndf(v2); v3 = rndf(v3);
            }
            *(float2*)(C + (size_t)row * N + col)       = make_float2(v0, v1);
            *(float2*)(C + (size_t)(row + 8) * N + col) = make_float2(v2, v3);
        }
    }
}

// ---------------------------------------------------------------------------
// Tensor-core attention: one block per (b,h), 256 threads. qkv is pre-
// rounded tf32 -> raw-bit fragment loads. P rounded once at smem store.
// ---------------------------------------------------------------------------
#define QLD 68
#define PLD2 132
#define VT_OFF 0
#define Q_OFF  (64 * PLD2)
#define K_OFF  (Q_OFF + 128 * QLD)
#define P_OFF  Q_OFF
#define PART_OFF (K_OFF + 128 * QLD)
#define RSUM_OFF (PART_OFF + 512)
#define ATTN_SMEMF (RSUM_OFF + 128)

__global__ __launch_bounds__(256)
void attn_kernel(const float* __restrict__ qkv,
                 const int* __restrict__ lens,
                 float* __restrict__ out) {
    const int bh = blockIdx.x;
    const int b  = bh / H_;
    const int h  = bh % H_;
    extern __shared__ float sm[];

    const int t    = threadIdx.x;
    const int lane = t & 31;
    const int wid  = t >> 5;
    const int g    = lane >> 2;
    const int tg   = lane & 3;
    const int len  = lens[b];

    for (int i4 = t; i4 < S_ * HD_ / 4; i4 += 256) {
        const int s  = i4 >> 4;
        const int d4 = i4 & 15;
        const float4* base =
            (const float4*)(qkv + (size_t)(b * S_ + s) * (3 * E_) + h * HD_);
        float4 qv = base[d4];
        float4 kv = base[(E_ / 4) + d4];
        float4 vv = base[(2 * E_ / 4) + d4];
        *(float4*)&sm[Q_OFF + s * QLD + d4 * 4] = qv;
        *(float4*)&sm[K_OFF + s * QLD + d4 * 4] = kv;
        const int d0 = d4 * 4;
        sm[VT_OFF + (d0 + 0) * PLD2 + s] = vv.x;
        sm[VT_OFF + (d0 + 1) * PLD2 + s] = vv.y;
        sm[VT_OFF + (d0 + 2) * PLD2 + s] = vv.z;
        sm[VT_OFF + (d0 + 3) * PLD2 + s] = vv.w;
    }
    __syncthreads();

    const uint32_t* smu = (const uint32_t*)sm;
    const int wm = (wid & 1) * 64;
    const int wn = (wid >> 1) * 32;
    float acc[4][4][4];
#pragma unroll
    for (int i = 0; i < 4; i++)
#pragma unroll
        for (int j = 0; j < 4; j++)
#pragma unroll
            for (int r = 0; r < 4; r++) acc[i][j][r] = 0.f;

#pragma unroll
    for (int ks = 0; ks < 8; ks++) {
        const int k0 = ks * 8;
        uint32_t af[4][4], bf[4][2];
#pragma unroll
        for (int mf = 0; mf < 4; mf++) {
            const int row = wm + mf * 16 + g;
            af[mf][0] = smu[Q_OFF + row * QLD + k0 + tg];
            af[mf][1] = smu[Q_OFF + (row + 8) * QLD + k0 + tg];
            af[mf][2] = smu[Q_OFF + row * QLD + k0 + tg + 4];
            af[mf][3] = smu[Q_OFF + (row + 8) * QLD + k0 + tg + 4];
        }
#pragma unroll
        for (int nf = 0; nf < 4; nf++) {
            const int col = wn + nf * 8 + g;
            bf[nf][0] = smu[K_OFF + col * QLD + k0 + tg];
            bf[nf][1] = smu[K_OFF + col * QLD + k0 + tg + 4];
        }
#pragma unroll
        for (int mf = 0; mf < 4; mf++)
#pragma unroll
            for (int nf = 0; nf < 4; nf++) MMA_TF32(acc[mf][nf], af[mf], bf[nf]);
    }

    float rs[4][2];
#pragma unroll
    for (int mf = 0; mf < 4; mf++) { rs[mf][0] = 0.f; rs[mf][1] = 0.f; }
#pragma unroll
    for (int mf = 0; mf < 4; mf++) {
#pragma unroll
        for (int nf = 0; nf < 4; nf++) {
            const int c0 = wn + nf * 8 + 2 * tg;
            const int c1 = c0 + 1;
            float* d = acc[mf][nf];
            d[0] = (c0 < len) ? __expf(d[0] * 0.125f) : 0.f;
            d[1] = (c1 < len) ? __expf(d[1] * 0.125f) : 0.f;
            d[2] = (c0 < len) ? __expf(d[2] * 0.125f) : 0.f;
            d[3] = (c1 < len) ? __expf(d[3] * 0.125f) : 0.f;
            rs[mf][0] += d[0] + d[1];
            rs[mf][1] += d[2] + d[3];
        }
#pragma unroll
        for (int o = 1; o < 4; o <<= 1) {
            rs[mf][0] += __shfl_xor_sync(0xffffffffu, rs[mf][0], o);
            rs[mf][1] += __shfl_xor_sync(0xffffffffu, rs[mf][1], o);
        }
    }
    __syncthreads();

    const int nidx = wid >> 1;
#pragma unroll
    for (int mf = 0; mf < 4; mf++) {
        const int r0 = wm + mf * 16 + g;
        const int r1 = r0 + 8;
#pragma unroll
        for (int nf = 0; nf < 4; nf++) {
            const int c0 = wn + nf * 8 + 2 * tg;
            const float* d = acc[mf][nf];
            *(float2*)&sm[P_OFF + r0 * PLD2 + c0] =
                make_float2(rndf(d[0]), rndf(d[1]));
            *(float2*)&sm[P_OFF + r1 * PLD2 + c0] =
                make_float2(rndf(d[2]), rndf(d[3]));
        }
        if (tg == 0) {
            sm[PART_OFF + r0 * 4 + nidx] = rs[mf][0];
            sm[PART_OFF + r1 * 4 + nidx] = rs[mf][1];
        }
    }
    __syncthreads();

    if (t < 128) {
        const float s = sm[PART_OFF + t * 4] + sm[PART_OFF + t * 4 + 1] +
                        sm[PART_OFF + t * 4 + 2] + sm[PART_OFF + t * 4 + 3];
        sm[RSUM_OFF + t] = 1.f / s;
    }
    __syncthreads();

    const int wm2 = (wid & 3) * 32;
    const int wn2 = (wid >> 2) * 32;
    float acc2[2][4][4];
#pragma unroll
    for (int i = 0; i < 2; i++)
#pragma unroll
        for (int j = 0; j < 4; j++)
#pragma unroll
            for (int r = 0; r < 4; r++) acc2[i][j][r] = 0.f;

#pragma unroll
    for (int ks = 0; ks < 16; ks++) {
        const int k0 = ks * 8;
        uint32_t af[2][4], bf[4][2];
#pragma unroll
        for (int mf = 0; mf < 2; mf++) {
            const int row = wm2 + mf * 16 + g;
            af[mf][0] = smu[P_OFF + row * PLD2 + k0 + tg];
            af[mf][1] = smu[P_OFF + (row + 8) * PLD2 + k0 + tg];
            af[mf][2] = smu[P_OFF + row * PLD2 + k0 + tg + 4];
            af[mf][3] = smu[P_OFF + (row + 8) * PLD2 + k0 + tg + 4];
        }
#pragma unroll
        for (int nf = 0; nf < 4; nf++) {
            const int col = wn2 + nf * 8 + g;
            bf[nf][0] = smu[VT_OFF + col * PLD2 + k0 + tg];
            bf[nf][1] = smu[VT_OFF + col * PLD2 + k0 + tg + 4];
        }
#pragma unroll
        for (int mf = 0; mf < 2; mf++)
#pragma unroll
            for (int nf = 0; nf < 4; nf++) MMA_TF32(acc2[mf][nf], af[mf], bf[nf]);
    }

    // normalize + round (feeds proj GEMM A) + store
#pragma unroll
    for (int mf = 0; mf < 2; mf++) {
        const int r0 = wm2 + mf * 16 + g;
        const int r1 = r0 + 8;
        const float i0 = sm[RSUM_OFF + r0];
        const float i1 = sm[RSUM_OFF + r1];
#pragma unroll
        for (int nf = 0; nf < 4; nf++) {
            const int c = wn2 + nf * 8 + 2 * tg;
            const float* d = acc2[mf][nf];
            *(float2*)(out + (size_t)(b * S_ + r0) * E_ + h * HD_ + c) =
                make_float2(rndf(d[0] * i0), rndf(d[1] * i0));
            *(float2*)(out + (size_t)(b * S_ + r1) * E_ + h * HD_ + c) =
                make_float2(rndf(d[2] * i1), rndf(d[3] * i1));
        }
    }
}

// ---------------------------------------------------------------------------
// Fused residual add + LayerNorm: warp per token; output tf32-rounded
// (feeds next GEMM A / pool).
// ---------------------------------------------------------------------------
__global__ __launch_bounds__(256)
void add_ln_kernel(const float* __restrict__ x, const float* __restrict__ y,
                   const float* __restrict__ sc, const float* __restrict__ bi,
                   float* __restrict__ out) {
    const int tok  = blockIdx.x * 8 + (threadIdx.x >> 5);
    const int lane = threadIdx.x & 31;
    const size_t base4 = (size_t)tok * (E_ / 4);

    float4 v0 = ((const float4*)x)[base4 + lane];
    float4 v1 = ((const float4*)x)[base4 + 32 + lane];
    float4 y0 = ((const float4*)y)[base4 + lane];
    float4 y1 = ((const float4*)y)[base4 + 32 + lane];
    v0.x += y0.x; v0.y += y0.y; v0.z += y0.z; v0.w += y0.w;
    v1.x += y1.x; v1.y += y1.y; v1.z += y1.z; v1.w += y1.w;

    float s = v0.x + v0.y + v0.z + v0.w + v1.x + v1.y + v1.z + v1.w;
#pragma unroll
    for (int o = 16; o; o >>= 1) s += __shfl_xor_sync(0xffffffffu, s, o);
    const float m = s * (1.f / E_);

    float q =
        (v0.x - m) * (v0.x - m) + (v0.y - m) * (v0.y - m) +
        (v0.z - m) * (v0.z - m) + (v0.w - m) * (v0.w - m) +
        (v1.x - m) * (v1.x - m) + (v1.y - m) * (v1.y - m) +
        (v1.z - m) * (v1.z - m) + (v1.w - m) * (v1.w - m);
#pragma unroll
    for (int o = 16; o; o >>= 1) q += __shfl_xor_sync(0xffffffffu, q, o);
    const float rstd = rsqrtf(q * (1.f / E_) + 1e-5f);

    const float4 s0 = ((const float4*)sc)[lane];
    const float4 s1 = ((const float4*)sc)[32 + lane];
    const float4 b0 = ((const float4*)bi)[lane];
    const float4 b1 = ((const float4*)bi)[32 + lane];
    float4 o0, o1;
    o0.x = rndf((v0.x - m) * rstd * s0.x + b0.x);
    o0.y = rndf((v0.y - m) * rstd * s0.y + b0.y);
    o0.z = rndf((v0.z - m) * rstd * s0.z + b0.z);
    o0.w = rndf((v0.w - m) * rstd * s0.w + b0.w);
    o1.x = rndf((v1.x - m) * rstd * s1.x + b1.x);
    o1.y = rndf((v1.y - m) * rstd * s1.y + b1.y);
    o1.z = rndf((v1.z - m) * rstd * s1.z + b1.z);
    o1.w = rndf((v1.w - m) * rstd * s1.w + b1.w);
    ((float4*)out)[base4 + lane]      = o0;
    ((float4*)out)[base4 + 32 + lane] = o1;
}

// ---------------------------------------------------------------------------
// Weighted pool + concat (+ per-sample sigmoid gate computed in-block)
// ---------------------------------------------------------------------------
__global__ __launch_bounds__(256)
void pool_kernel(const float* __restrict__ x, const float* __restrict__ attr_tf,
                 const int* __restrict__ lens, const int* __restrict__ lens_user,
                 const float* __restrict__ feat, const float* __restrict__ fW,
                 const float* __restrict__ fb,
                 const int* __restrict__ user_ids, const int* __restrict__ item_ids,
                 const float* __restrict__ user_emb, const float* __restrict__ item_emb,
                 float* __restrict__ out) {
    const int b = blockIdx.x;
    const int e = threadIdx.x;
    __shared__ float w[S_];
    __shared__ float wu_s;
    if (e == 0) {
        float z = fb[0];
#pragma unroll
        for (int i = 0; i < 13; i++) z += feat[b * 13 + i] * fW[i];
        wu_s = 1.f / (1.f + expf(-z));
    }
    __syncthreads();
    if (e < S_) {
        const int s = e;
        float wgt = 0.f;
        if (s < lens[b]) {
            const float g = (s < lens_user[b]) ? wu_s : (1.f - wu_s);
            wgt = attr_tf[b * S_ + s] * g;
        }
        w[s] = wgt;
    }
    __syncthreads();
    float acc = 0.f;
    const float* xb = x + (size_t)b * S_ * E_ + e;
    for (int s = 0; s < S_; s++) acc += w[s] * xb[(size_t)s * E_];
    out[(size_t)b * 3 * E_ + E_ + e]     = acc;
    out[(size_t)b * 3 * E_ + e]          = user_emb[(size_t)user_ids[b] * E_ + e];
    out[(size_t)b * 3 * E_ + 2 * E_ + e] = item_emb[(size_t)item_ids[b] * E_ + e];
}

// ---------------------------------------------------------------------------
// Scoring head: one warp per PAIR of targets (j, j+300).
// ---------------------------------------------------------------------------
__global__ __launch_bounds__(256)
void logits_kernel(const float* __restrict__ outv, const float* __restrict__ out_emb,
                   const int* __restrict__ pos_t, const int* __restrict__ pos_l,
                   const int* __restrict__ neg_t, const int* __restrict__ neg_l,
                   float* __restrict__ dout) {
    const int gw   = (int)((blockIdx.x * blockDim.x + threadIdx.x) >> 5);
    const int lane = threadIdx.x & 31;
    if (gw >= B_ * NTH_) return;
    const int b  = gw / NTH_;
    const int j1 = gw % NTH_;
    const int j2 = j1 + NTH_;

    const int pl = pos_l[b];
    const int nl = neg_l[b];

    int tgt1; float valid1, posf1;
    if (j1 < P_) {
        tgt1 = pos_t[b * P_ + j1]; valid1 = (j1 < pl) ? 1.f : 0.f; posf1 = 1.f;
    } else {
        const int jn = j1 - P_;
        tgt1 = neg_t[b * N_ + jn]; valid1 = (jn < nl) ? 1.f : 0.f; posf1 = 0.f;
    }
    int tgt2; float valid2, posf2;
    {
        const int jn = j2 - P_;
        tgt2 = neg_t[b * N_ + jn]; valid2 = (jn < nl) ? 1.f : 0.f; posf2 = 0.f;
    }

    const float4* ovs = (const float4*)(outv + (size_t)b * (3 * E_));
    const float4* e1  = (const float4*)(out_emb + (size_t)tgt1 * (3 * E_));
    const float4* e2  = (const float4*)(out_emb + (size_t)tgt2 * (3 * E_));
    float a1 = 0.f, a2 = 0.f;
#pragma unroll
    for (int i = 0; i < 6; i++) {
        const int k4 = lane + i * 32;
        const float4 c  = ovs[k4];
        const float4 r1 = e1[k4];
        const float4 r2 = e2[k4];
        a1 += r1.x * c.x + r1.y * c.y + r1.z * c.z + r1.w * c.w;
        a2 += r2.x * c.x + r2.y * c.y + r2.z * c.z + r2.w * c.w;
    }
#pragma unroll
    for (int o = 16; o; o >>= 1) {
        a1 += __shfl_xor_sync(0xffffffffu, a1, o);
        a2 += __shfl_xor_sync(0xffffffffu, a2, o);
    }
    if (lane == 0) {
        const int idx1 = b * NT_ + j1;
        const int idx2 = b * NT_ + j2;
        dout[idx1]                = a1;
        dout[B_ * NT_ + idx1]     = valid1;
        dout[2 * B_ * NT_ + idx1] = posf1 * valid1;
        dout[idx2]                = a2;
        dout[B_ * NT_ + idx2]     = valid2;
        dout[2 * B_ * NT_ + idx2] = posf2 * valid2;
    }
}

// ---------------------------------------------------------------------------
// Launch
// ---------------------------------------------------------------------------
extern "C" void kernel_launch(void* const* d_in, const int* in_sizes, int n_in,
                              void* d_out, int out_size) {
    const int*   attr           = (const int*)  d_in[0];
    const float* attr_tf        = (const float*)d_in[2];
    const float* attr_feat      = (const float*)d_in[3];
    const int*   attr_lens      = (const int*)  d_in[4];
    const int*   attr_lens_user = (const int*)  d_in[5];
    const int*   user_ids       = (const int*)  d_in[7];
    const int*   item_ids       = (const int*)  d_in[8];
    const int*   pos_targets    = (const int*)  d_in[9];
    const int*   pos_lens       = (const int*)  d_in[10];
    const int*   neg_targets    = (const int*)  d_in[11];
    const int*   neg_lens       = (const int*)  d_in[12];
    const float* attr_emb       = (const float*)d_in[13];
    const float* user_emb       = (const float*)d_in[14];
    const float* item_emb       = (const float*)d_in[15];
    const float* out_emb        = (const float*)d_in[16];
    const float* fw_W           = (const float*)d_in[17];
    const float* fw_b           = (const float*)d_in[18];
    const float* qkv_w          = (const float*)d_in[19];
    const float* qkv_b          = (const float*)d_in[20];
    const float* attn_out_w     = (const float*)d_in[21];
    const float* attn_out_b     = (const float*)d_in[22];
    const float* ln1_s          = (const float*)d_in[23];
    const float* ln1_b          = (const float*)d_in[24];
    const float* ff1_w          = (const float*)d_in[25];
    const float* ff1_b          = (const float*)d_in[26];
    const float* ff2_w          = (const float*)d_in[27];
    const float* ff2_b          = (const float*)d_in[28];
    const float* ln2_s          = (const float*)d_in[29];
    const float* ln2_b          = (const float*)d_in[30];

    float *x, *qkv, *attn, *tmp, *ff, *outv, *wr;
    cudaGetSymbolAddress((void**)&x,    g_x);
    cudaGetSymbolAddress((void**)&qkv,  g_qkv);
    cudaGetSymbolAddress((void**)&attn, g_attn);
    cudaGetSymbolAddress((void**)&tmp,  g_tmp);
    cudaGetSymbolAddress((void**)&ff,   g_ff);
    cudaGetSymbolAddress((void**)&outv, g_out);
    cudaGetSymbolAddress((void**)&wr,   g_wr);

    const int gemm_smem = STAGES * 2 * TSZ * (int)sizeof(float);   // 61440
    cudaFuncSetAttribute(tgemm<false, true>, cudaFuncAttributeMaxDynamicSharedMemorySize,
                         gemm_smem);
    cudaFuncSetAttribute(tgemm<false, false>, cudaFuncAttributeMaxDynamicSharedMemorySize,
                         gemm_smem);
    cudaFuncSetAttribute(tgemm<true, true>, cudaFuncAttributeMaxDynamicSharedMemorySize,
                         gemm_smem);
    const int attn_smem = ATTN_SMEMF * (int)sizeof(float);         // 105984
    cudaFuncSetAttribute(attn_kernel, cudaFuncAttributeMaxDynamicSharedMemorySize,
                         attn_smem);

    // pre-round weights into g_wr
    round_w_kernel<<<1536, 256>>>((const float4*)qkv_w, (const float4*)attn_out_w,
                                  (const float4*)ff1_w, (const float4*)ff2_w,
                                  (float4*)wr);
    gather_kernel<<<(T_ * E_ / 4 + 255) / 256, 256>>>(attr, attr_emb, x);

    for (int l = 0; l < L_; l++) {
        const float* lqkv_w = wr + WR_QKV + (size_t)l * 3 * E_ * E_;
        const float* lao_w  = wr + WR_AO  + (size_t)l * E_ * E_;
        const float* lf1_w  = wr + WR_FF1 + (size_t)l * F_ * E_;
        const float* lf2_w  = wr + WR_FF2 + (size_t)l * E_ * F_;
        const float* lqkv_b = qkv_b      + (size_t)l * 3 * E_;
        const float* lao_b  = attn_out_b + (size_t)l * E_;
        const float* l1s    = ln1_s + (size_t)l * E_;
        const float* l1b    = ln1_b + (size_t)l * E_;
        const float* lf1_b  = ff1_b + (size_t)l * F_;
        const float* lf2_b  = ff2_b + (size_t)l * E_;
        const float* l2s    = ln2_s + (size_t)l * E_;
        const float* l2b    = ln2_b + (size_t)l * E_;

        tgemm<false, true><<<dim3(3 * E_ / 128, T_ / 128), 256, gemm_smem>>>(
            x, lqkv_w, lqkv_b, qkv, T_, 3 * E_, E_);
        attn_kernel<<<B_ * H_, 256, attn_smem>>>(qkv, attr_lens, attn);
        tgemm<false, false><<<dim3(E_ / 128, T_ / 128), 256, gemm_smem>>>(
            attn, lao_w, lao_b, tmp, T_, E_, E_);
        add_ln_kernel<<<T_ / 8, 256>>>(x, tmp, l1s, l1b, x);
        tgemm<true, true><<<dim3(F_ / 128, T_ / 128), 256, gemm_smem>>>(
            x, lf1_w, lf1_b, ff, T_, F_, E_);
        tgemm<false, false><<<dim3(E_ / 128, T_ / 128), 256, gemm_smem>>>(
            ff, lf2_w, lf2_b, tmp, T_, E_, F_);
        add_ln_kernel<<<T_ / 8, 256>>>(x, tmp, l2s, l2b, x);
    }

    pool_kernel<<<B_, 256>>>(x, attr_tf, attr_lens, attr_lens_user,
                             attr_feat, fw_W, fw_b,
                             user_ids, item_ids, user_emb, item_emb, outv);

    const int nwarps = B_ * NTH_;                      // 76800
    logits_kernel<<<(nwarps * 32 + 255) / 256, 256>>>(
        outv, out_emb, pos_targets, pos_lens, neg_targets, neg_lens,
        (float*)d_out);
}

// round 12
// speedup vs baseline: 1.1176x; 1.0393x over previous
#include <cuda_runtime.h>
#include <cuda_bf16.h>
#include <math.h>
#include <stdint.h>

// Problem constants
#define B_   256
#define S_   128
#define P_   100
#define N_   500
#define E_   256
#define H_   4
#define HD_  64
#define L_   2
#define F_   1024
#define T_   (B_ * S_)      // 32768 tokens
#define NT_  (P_ + N_)      // 600 targets
#define NTH_ (NT_ / 2)      // 300 pairs per sample

// ---------------------------------------------------------------------------
// Scratch (device globals — no allocation allowed)
// ---------------------------------------------------------------------------
__device__ float g_x   [(size_t)T_ * E_];
__device__ float g_qkv [(size_t)T_ * 3 * E_];
__device__ float g_attn[(size_t)T_ * E_];
__device__ float g_tmp [(size_t)T_ * E_];
__device__ float g_ff  [(size_t)T_ * F_];
__device__ float g_out [(size_t)B_ * 3 * E_];
__device__ float g_wr  [1572864];             // tf32-rounded weights (6MB)

#define WR_QKV 0
#define WR_AO  393216
#define WR_FF1 524288
#define WR_FF2 1048576

// ---------------------------------------------------------------------------
// cp.async + tf32 helpers
// ---------------------------------------------------------------------------
__device__ __forceinline__ void cp16(void* sdst, const void* gsrc) {
    uint32_t s = (uint32_t)__cvta_generic_to_shared(sdst);
    asm volatile("cp.async.cg.shared.global [%0], [%1], 16;\n" :: "r"(s), "l"(gsrc));
}
__device__ __forceinline__ void cp_commit() {
    asm volatile("cp.async.commit_group;\n");
}
template<int NWait>
__device__ __forceinline__ void cp_wait() {
    asm volatile("cp.async.wait_group %0;\n" :: "n"(NWait));
}
__device__ __forceinline__ float rndf(float x) {
    uint32_t r;
    asm("cvt.rna.tf32.f32 %0, %1;" : "=r"(r) : "f"(x));
    return __uint_as_float(r);
}
#define MMA_TF32(d, a, b)                                                     \
    asm volatile(                                                             \
        "mma.sync.aligned.m16n8k8.row.col.f32.tf32.tf32.f32 "                 \
        "{%0,%1,%2,%3}, {%4,%5,%6,%7}, {%8,%9}, {%0,%1,%2,%3};"               \
        : "+f"(d[0]), "+f"(d[1]), "+f"(d[2]), "+f"(d[3])                      \
        : "r"(a[0]), "r"(a[1]), "r"(a[2]), "r"(a[3]), "r"(b[0]), "r"(b[1]))

// ---------------------------------------------------------------------------
// Weight pre-rounding
// ---------------------------------------------------------------------------
__global__ void round_w_kernel(const float4* __restrict__ qkvw,
                               const float4* __restrict__ aow,
                               const float4* __restrict__ f1w,
                               const float4* __restrict__ f2w,
                               float4* __restrict__ dst) {
    const int i = blockIdx.x * blockDim.x + threadIdx.x;
    if (i >= 393216) return;
    float4 v;
    int o = i;
    if (o < 98304)               v = qkvw[o];
    else if ((o -= 98304) < 32768)  v = aow[o];
    else if ((o -= 32768) < 131072) v = f1w[o];
    else                          v = f2w[o - 131072];
    v.x = rndf(v.x); v.y = rndf(v.y); v.z = rndf(v.z); v.w = rndf(v.w);
    dst[i] = v;
}

// ---------------------------------------------------------------------------
// Embedding gather (float4), output rounded to tf32
// ---------------------------------------------------------------------------
__global__ void gather_kernel(const int* __restrict__ attr,
                              const float* __restrict__ emb,
                              float* __restrict__ x) {
    int i4 = blockIdx.x * blockDim.x + threadIdx.x;
    if (i4 < T_ * (E_ / 4)) {
        int t = i4 >> 6;
        int e4 = i4 & 63;
        float4 v = ((const float4*)emb)[(size_t)attr[t] * (E_ / 4) + e4];
        v.x = rndf(v.x); v.y = rndf(v.y); v.z = rndf(v.z); v.w = rndf(v.w);
        ((float4*)x)[i4] = v;
    }
}

// ---------------------------------------------------------------------------
// TF32 GEMM (R11-proven): pre-rounded inputs, no cvt in inner loop.
// Block 128x128, BK=16, 8 warps of 64x32, 3-stage cp.async, 2 CTAs/SM.
// ---------------------------------------------------------------------------
#define LDA    20
#define TSZ    (128 * LDA)
#define STAGES 3

template<bool RELU, bool ROUND>
__global__ __launch_bounds__(256, 2)
void tgemm(const float* __restrict__ A, const float* __restrict__ Bm,
           const float* __restrict__ bias, float* __restrict__ C,
           int M, int N, int K) {
    extern __shared__ float smw[];
    float* As = smw;
    float* Bs = smw + STAGES * TSZ;

    const int bm   = blockIdx.y * 128;
    const int bn   = blockIdx.x * 128;
    const int t    = threadIdx.x;
    const int lane = t & 31;
    const int wid  = t >> 5;
    const int wm   = (wid & 1) * 64;
    const int wn   = (wid >> 1) * 32;
    const int g    = lane >> 2;
    const int tg   = lane & 3;

    const int lrow = t >> 1;
    const int lkb  = (t & 1) * 8;
    const float* Ap = A  + (size_t)(bm + lrow) * K + lkb;
    const float* Bp = Bm + (size_t)(bn + lrow) * K + lkb;

    float acc[4][4][4];
#pragma unroll
    for (int i = 0; i < 4; i++)
#pragma unroll
        for (int j = 0; j < 4; j++)
#pragma unroll
            for (int r = 0; r < 4; r++) acc[i][j][r] = 0.f;

    const int nk = K >> 4;
#pragma unroll
    for (int s = 0; s < STAGES - 1; s++) {
        const int k0 = s << 4;
        cp16(&As[s * TSZ + lrow * LDA + lkb],     Ap + k0);
        cp16(&As[s * TSZ + lrow * LDA + lkb + 4], Ap + k0 + 4);
        cp16(&Bs[s * TSZ + lrow * LDA + lkb],     Bp + k0);
        cp16(&Bs[s * TSZ + lrow * LDA + lkb + 4], Bp + k0 + 4);
        cp_commit();
    }

    int cur = 0;
    for (int kt = 0; kt < nk; kt++) {
        if (kt < nk - 1) cp_wait<STAGES - 2>(); else cp_wait<0>();
        __syncthreads();

        const uint32_t* Ac = (const uint32_t*)(As + cur * TSZ);
        const uint32_t* Bc = (const uint32_t*)(Bs + cur * TSZ);
#pragma unroll
        for (int ks = 0; ks < 2; ks++) {
            const int k0 = ks * 8;
            uint32_t af[4][4], bf[4][2];
#pragma unroll
            for (int mf = 0; mf < 4; mf++) {
                const int row = wm + mf * 16 + g;
                af[mf][0] = Ac[row * LDA + k0 + tg];
                af[mf][1] = Ac[(row + 8) * LDA + k0 + tg];
                af[mf][2] = Ac[row * LDA + k0 + tg + 4];
                af[mf][3] = Ac[(row + 8) * LDA + k0 + tg + 4];
            }
#pragma unroll
            for (int nf = 0; nf < 4; nf++) {
                const int col = wn + nf * 8 + g;
                bf[nf][0] = Bc[col * LDA + k0 + tg];
                bf[nf][1] = Bc[col * LDA + k0 + tg + 4];
            }
#pragma unroll
            for (int mf = 0; mf < 4; mf++)
#pragma unroll
                for (int nf = 0; nf < 4; nf++) MMA_TF32(acc[mf][nf], af[mf], bf[nf]);
        }

        const int pf = kt + STAGES - 1;
        if (pf < nk) {
            const int ps = pf % STAGES;
            const int k0 = pf << 4;
            cp16(&As[ps * TSZ + lrow * LDA + lkb],     Ap + k0);
            cp16(&As[ps * TSZ + lrow * LDA + lkb + 4], Ap + k0 + 4);
            cp16(&Bs[ps * TSZ + lrow * LDA + lkb],     Bp + k0);
            cp16(&Bs[ps * TSZ + lrow * LDA + lkb + 4], Bp + k0 + 4);
            cp_commit();
        }
        cur = (cur + 1 == STAGES) ? 0 : cur + 1;
    }

#pragma unroll
    for (int nf = 0; nf < 4; nf++) {
        const int col = bn + wn + nf * 8 + 2 * tg;
        const float b0v = bias[col], b1v = bias[col + 1];
#pragma unroll
        for (int mf = 0; mf < 4; mf++) {
            const int row = bm + wm + mf * 16 + g;
            float v0 = acc[mf][nf][0] + b0v;
            float v1 = acc[mf][nf][1] + b1v;
            float v2 = acc[mf][nf][2] + b0v;
            float v3 = acc[mf][nf][3] + b1v;
            if (RELU) {
                v0 = fmaxf(v0, 0.f); v1 = fmaxf(v1, 0.f);
                v2 = fmaxf(v2, 0.f); v3 = fmaxf(v3, 0.f);
            }
            if (ROUND) {
                v0 = rndf(v0); v1 = rndf(v1); v2 = rndf(v2); v3 = rndf(v3);
            }
            *(float2*)(C + (size_t)row * N + col)       = make_float2(v0, v1);
            *(float2*)(C + (size_t)(row + 8) * N + col) = make_float2(v2, v3);
        }
    }
}

// ---------------------------------------------------------------------------
// Tensor-core attention v2: one block per (b,h), 512 threads (16 warps).
// Smaller warp tiles -> ~half the regs/thread of the 256-thr version ->
// 16 warps resident per SM (vs 8): double latency coverage.
// Phase 1: S=Q@K^T, warp tile 32x32 (4x4 warp grid), acc[2][4][4].
// Phase 2: O=P@V,   warp tile 16x32 (8x2 warp grid), acc2[1][4][4].
// ---------------------------------------------------------------------------
#define QLD 68
#define PLD2 132
#define VT_OFF 0
#define Q_OFF  (64 * PLD2)
#define K_OFF  (Q_OFF + 128 * QLD)
#define P_OFF  Q_OFF
#define PART_OFF (K_OFF + 128 * QLD)
#define RSUM_OFF (PART_OFF + 512)
#define ATTN_SMEMF (RSUM_OFF + 128)

__global__ __launch_bounds__(512)
void attn_kernel(const float* __restrict__ qkv,
                 const int* __restrict__ lens,
                 float* __restrict__ out) {
    const int bh = blockIdx.x;
    const int b  = bh / H_;
    const int h  = bh % H_;
    extern __shared__ float sm[];

    const int t    = threadIdx.x;
    const int lane = t & 31;
    const int wid  = t >> 5;           // 0..15
    const int g    = lane >> 2;
    const int tg   = lane & 3;
    const int len  = lens[b];

    for (int i4 = t; i4 < S_ * HD_ / 4; i4 += 512) {
        const int s  = i4 >> 4;
        const int d4 = i4 & 15;
        const float4* base =
            (const float4*)(qkv + (size_t)(b * S_ + s) * (3 * E_) + h * HD_);
        float4 qv = base[d4];
        float4 kv = base[(E_ / 4) + d4];
        float4 vv = base[(2 * E_ / 4) + d4];
        *(float4*)&sm[Q_OFF + s * QLD + d4 * 4] = qv;
        *(float4*)&sm[K_OFF + s * QLD + d4 * 4] = kv;
        const int d0 = d4 * 4;
        sm[VT_OFF + (d0 + 0) * PLD2 + s] = vv.x;
        sm[VT_OFF + (d0 + 1) * PLD2 + s] = vv.y;
        sm[VT_OFF + (d0 + 2) * PLD2 + s] = vv.z;
        sm[VT_OFF + (d0 + 3) * PLD2 + s] = vv.w;
    }
    __syncthreads();

    const uint32_t* smu = (const uint32_t*)sm;
    // ---- phase 1: warp tile 32(q) x 32(k), 4x4 warp grid ----
    const int wm = (wid & 3) * 32;
    const int wn = (wid >> 2) * 32;
    float acc[2][4][4];
#pragma unroll
    for (int i = 0; i < 2; i++)
#pragma unroll
        for (int j = 0; j < 4; j++)
#pragma unroll
            for (int r = 0; r < 4; r++) acc[i][j][r] = 0.f;

#pragma unroll
    for (int ks = 0; ks < 8; ks++) {
        const int k0 = ks * 8;
        uint32_t af[2][4], bf[4][2];
#pragma unroll
        for (int mf = 0; mf < 2; mf++) {
            const int row = wm + mf * 16 + g;
            af[mf][0] = smu[Q_OFF + row * QLD + k0 + tg];
            af[mf][1] = smu[Q_OFF + (row + 8) * QLD + k0 + tg];
            af[mf][2] = smu[Q_OFF + row * QLD + k0 + tg + 4];
            af[mf][3] = smu[Q_OFF + (row + 8) * QLD + k0 + tg + 4];
        }
#pragma unroll
        for (int nf = 0; nf < 4; nf++) {
            const int col = wn + nf * 8 + g;
            bf[nf][0] = smu[K_OFF + col * QLD + k0 + tg];
            bf[nf][1] = smu[K_OFF + col * QLD + k0 + tg + 4];
        }
#pragma unroll
        for (int mf = 0; mf < 2; mf++)
#pragma unroll
            for (int nf = 0; nf < 4; nf++) MMA_TF32(acc[mf][nf], af[mf], bf[nf]);
    }

    // exp + row partial sums
    float rs[2][2];
#pragma unroll
    for (int mf = 0; mf < 2; mf++) { rs[mf][0] = 0.f; rs[mf][1] = 0.f; }
#pragma unroll
    for (int mf = 0; mf < 2; mf++) {
#pragma unroll
        for (int nf = 0; nf < 4; nf++) {
            const int c0 = wn + nf * 8 + 2 * tg;
            const int c1 = c0 + 1;
            float* d = acc[mf][nf];
            d[0] = (c0 < len) ? __expf(d[0] * 0.125f) : 0.f;
            d[1] = (c1 < len) ? __expf(d[1] * 0.125f) : 0.f;
            d[2] = (c0 < len) ? __expf(d[2] * 0.125f) : 0.f;
            d[3] = (c1 < len) ? __expf(d[3] * 0.125f) : 0.f;
            rs[mf][0] += d[0] + d[1];
            rs[mf][1] += d[2] + d[3];
        }
#pragma unroll
        for (int o = 1; o < 4; o <<= 1) {
            rs[mf][0] += __shfl_xor_sync(0xffffffffu, rs[mf][0], o);
            rs[mf][1] += __shfl_xor_sync(0xffffffffu, rs[mf][1], o);
        }
    }
    __syncthreads();   // Q/K reads done -> overlay with P

    const int nidx = wid >> 2;   // 32-key slab 0..3
#pragma unroll
    for (int mf = 0; mf < 2; mf++) {
        const int r0 = wm + mf * 16 + g;
        const int r1 = r0 + 8;
#pragma unroll
        for (int nf = 0; nf < 4; nf++) {
            const int c0 = wn + nf * 8 + 2 * tg;
            const float* d = acc[mf][nf];
            *(float2*)&sm[P_OFF + r0 * PLD2 + c0] =
                make_float2(rndf(d[0]), rndf(d[1]));
            *(float2*)&sm[P_OFF + r1 * PLD2 + c0] =
                make_float2(rndf(d[2]), rndf(d[3]));
        }
        if (tg == 0) {
            sm[PART_OFF + r0 * 4 + nidx] = rs[mf][0];
            sm[PART_OFF + r1 * 4 + nidx] = rs[mf][1];
        }
    }
    __syncthreads();

    if (t < 128) {
        const float s = sm[PART_OFF + t * 4] + sm[PART_OFF + t * 4 + 1] +
                        sm[PART_OFF + t * 4 + 2] + sm[PART_OFF + t * 4 + 3];
        sm[RSUM_OFF + t] = 1.f / s;
    }
    __syncthreads();

    // ---- phase 2: warp tile 16(q) x 32(d), 8x2 warp grid ----
    const int wm2 = (wid & 7) * 16;
    const int wn2 = (wid >> 3) * 32;
    float acc2[4][4];
#pragma unroll
    for (int j = 0; j < 4; j++)
#pragma unroll
        for (int r = 0; r < 4; r++) acc2[j][r] = 0.f;

#pragma unroll
    for (int ks = 0; ks < 16; ks++) {
        const int k0 = ks * 8;
        uint32_t af[4], bf[4][2];
        {
            const int row = wm2 + g;
            af[0] = smu[P_OFF + row * PLD2 + k0 + tg];
            af[1] = smu[P_OFF + (row + 8) * PLD2 + k0 + tg];
            af[2] = smu[P_OFF + row * PLD2 + k0 + tg + 4];
            af[3] = smu[P_OFF + (row + 8) * PLD2 + k0 + tg + 4];
        }
#pragma unroll
        for (int nf = 0; nf < 4; nf++) {
            const int col = wn2 + nf * 8 + g;
            bf[nf][0] = smu[VT_OFF + col * PLD2 + k0 + tg];
            bf[nf][1] = smu[VT_OFF + col * PLD2 + k0 + tg + 4];
        }
#pragma unroll
        for (int nf = 0; nf < 4; nf++) MMA_TF32(acc2[nf], af, bf[nf]);
    }

    // normalize + round + store
    {
        const int r0 = wm2 + g;
        const int r1 = r0 + 8;
        const float i0 = sm[RSUM_OFF + r0];
        const float i1 = sm[RSUM_OFF + r1];
#pragma unroll
        for (int nf = 0; nf < 4; nf++) {
            const int c = wn2 + nf * 8 + 2 * tg;
            const float* d = acc2[nf];
            *(float2*)(out + (size_t)(b * S_ + r0) * E_ + h * HD_ + c) =
                make_float2(rndf(d[0] * i0), rndf(d[1] * i0));
            *(float2*)(out + (size_t)(b * S_ + r1) * E_ + h * HD_ + c) =
                make_float2(rndf(d[2] * i1), rndf(d[3] * i1));
        }
    }
}

// ---------------------------------------------------------------------------
// Fused residual add + LayerNorm: warp per token; output tf32-rounded
// ---------------------------------------------------------------------------
__global__ __launch_bounds__(256)
void add_ln_kernel(const float* __restrict__ x, const float* __restrict__ y,
                   const float* __restrict__ sc, const float* __restrict__ bi,
                   float* __restrict__ out) {
    const int tok  = blockIdx.x * 8 + (threadIdx.x >> 5);
    const int lane = threadIdx.x & 31;
    const size_t base4 = (size_t)tok * (E_ / 4);

    float4 v0 = ((const float4*)x)[base4 + lane];
    float4 v1 = ((const float4*)x)[base4 + 32 + lane];
    float4 y0 = ((const float4*)y)[base4 + lane];
    float4 y1 = ((const float4*)y)[base4 + 32 + lane];
    v0.x += y0.x; v0.y += y0.y; v0.z += y0.z; v0.w += y0.w;
    v1.x += y1.x; v1.y += y1.y; v1.z += y1.z; v1.w += y1.w;

    float s = v0.x + v0.y + v0.z + v0.w + v1.x + v1.y + v1.z + v1.w;
#pragma unroll
    for (int o = 16; o; o >>= 1) s += __shfl_xor_sync(0xffffffffu, s, o);
    const float m = s * (1.f / E_);

    float q =
        (v0.x - m) * (v0.x - m) + (v0.y - m) * (v0.y - m) +
        (v0.z - m) * (v0.z - m) + (v0.w - m) * (v0.w - m) +
        (v1.x - m) * (v1.x - m) + (v1.y - m) * (v1.y - m) +
        (v1.z - m) * (v1.z - m) + (v1.w - m) * (v1.w - m);
#pragma unroll
    for (int o = 16; o; o >>= 1) q += __shfl_xor_sync(0xffffffffu, q, o);
    const float rstd = rsqrtf(q * (1.f / E_) + 1e-5f);

    const float4 s0 = ((const float4*)sc)[lane];
    const float4 s1 = ((const float4*)sc)[32 + lane];
    const float4 b0 = ((const float4*)bi)[lane];
    const float4 b1 = ((const float4*)bi)[32 + lane];
    float4 o0, o1;
    o0.x = rndf((v0.x - m) * rstd * s0.x + b0.x);
    o0.y = rndf((v0.y - m) * rstd * s0.y + b0.y);
    o0.z = rndf((v0.z - m) * rstd * s0.z + b0.z);
    o0.w = rndf((v0.w - m) * rstd * s0.w + b0.w);
    o1.x = rndf((v1.x - m) * rstd * s1.x + b1.x);
    o1.y = rndf((v1.y - m) * rstd * s1.y + b1.y);
    o1.z = rndf((v1.z - m) * rstd * s1.z + b1.z);
    o1.w = rndf((v1.w - m) * rstd * s1.w + b1.w);
    ((float4*)out)[base4 + lane]      = o0;
    ((float4*)out)[base4 + 32 + lane] = o1;
}

// ---------------------------------------------------------------------------
// Weighted pool + concat (+ sigmoid gate)
// ---------------------------------------------------------------------------
__global__ __launch_bounds__(256)
void pool_kernel(const float* __restrict__ x, const float* __restrict__ attr_tf,
                 const int* __restrict__ lens, const int* __restrict__ lens_user,
                 const float* __restrict__ feat, const float* __restrict__ fW,
                 const float* __restrict__ fb,
                 const int* __restrict__ user_ids, const int* __restrict__ item_ids,
                 const float* __restrict__ user_emb, const float* __restrict__ item_emb,
                 float* __restrict__ out) {
    const int b = blockIdx.x;
    const int e = threadIdx.x;
    __shared__ float w[S_];
    __shared__ float wu_s;
    if (e == 0) {
        float z = fb[0];
#pragma unroll
        for (int i = 0; i < 13; i++) z += feat[b * 13 + i] * fW[i];
        wu_s = 1.f / (1.f + expf(-z));
    }
    __syncthreads();
    if (e < S_) {
        const int s = e;
        float wgt = 0.f;
        if (s < lens[b]) {
            const float g = (s < lens_user[b]) ? wu_s : (1.f - wu_s);
            wgt = attr_tf[b * S_ + s] * g;
        }
        w[s] = wgt;
    }
    __syncthreads();
    float acc = 0.f;
    const float* xb = x + (size_t)b * S_ * E_ + e;
    for (int s = 0; s < S_; s++) acc += w[s] * xb[(size_t)s * E_];
    out[(size_t)b * 3 * E_ + E_ + e]     = acc;
    out[(size_t)b * 3 * E_ + e]          = user_emb[(size_t)user_ids[b] * E_ + e];
    out[(size_t)b * 3 * E_ + 2 * E_ + e] = item_emb[(size_t)item_ids[b] * E_ + e];
}

// ---------------------------------------------------------------------------
// Scoring head: one warp per PAIR of targets (j, j+300)
// ---------------------------------------------------------------------------
__global__ __launch_bounds__(256)
void logits_kernel(const float* __restrict__ outv, const float* __restrict__ out_emb,
                   const int* __restrict__ pos_t, const int* __restrict__ pos_l,
                   const int* __restrict__ neg_t, const int* __restrict__ neg_l,
                   float* __restrict__ dout) {
    const int gw   = (int)((blockIdx.x * blockDim.x + threadIdx.x) >> 5);
    const int lane = threadIdx.x & 31;
    if (gw >= B_ * NTH_) return;
    const int b  = gw / NTH_;
    const int j1 = gw % NTH_;
    const int j2 = j1 + NTH_;

    const int pl = pos_l[b];
    const int nl = neg_l[b];

    int tgt1; float valid1, posf1;
    if (j1 < P_) {
        tgt1 = pos_t[b * P_ + j1]; valid1 = (j1 < pl) ? 1.f : 0.f; posf1 = 1.f;
    } else {
        const int jn = j1 - P_;
        tgt1 = neg_t[b * N_ + jn]; valid1 = (jn < nl) ? 1.f : 0.f; posf1 = 0.f;
    }
    int tgt2; float valid2, posf2;
    {
        const int jn = j2 - P_;
        tgt2 = neg_t[b * N_ + jn]; valid2 = (jn < nl) ? 1.f : 0.f; posf2 = 0.f;
    }

    const float4* ovs = (const float4*)(outv + (size_t)b * (3 * E_));
    const float4* e1  = (const float4*)(out_emb + (size_t)tgt1 * (3 * E_));
    const float4* e2  = (const float4*)(out_emb + (size_t)tgt2 * (3 * E_));
    float a1 = 0.f, a2 = 0.f;
#pragma unroll
    for (int i = 0; i < 6; i++) {
        const int k4 = lane + i * 32;
        const float4 c  = ovs[k4];
        const float4 r1 = e1[k4];
        const float4 r2 = e2[k4];
        a1 += r1.x * c.x + r1.y * c.y + r1.z * c.z + r1.w * c.w;
        a2 += r2.x * c.x + r2.y * c.y + r2.z * c.z + r2.w * c.w;
    }
#pragma unroll
    for (int o = 16; o; o >>= 1) {
        a1 += __shfl_xor_sync(0xffffffffu, a1, o);
        a2 += __shfl_xor_sync(0xffffffffu, a2, o);
    }
    if (lane == 0) {
        const int idx1 = b * NT_ + j1;
        const int idx2 = b * NT_ + j2;
        dout[idx1]                = a1;
        dout[B_ * NT_ + idx1]     = valid1;
        dout[2 * B_ * NT_ + idx1] = posf1 * valid1;
        dout[idx2]                = a2;
        dout[B_ * NT_ + idx2]     = valid2;
        dout[2 * B_ * NT_ + idx2] = posf2 * valid2;
    }
}

// ---------------------------------------------------------------------------
// Launch
// ---------------------------------------------------------------------------
extern "C" void kernel_launch(void* const* d_in, const int* in_sizes, int n_in,
                              void* d_out, int out_size) {
    const int*   attr           = (const int*)  d_in[0];
    const float* attr_tf        = (const float*)d_in[2];
    const float* attr_feat      = (const float*)d_in[3];
    const int*   attr_lens      = (const int*)  d_in[4];
    const int*   attr_lens_user = (const int*)  d_in[5];
    const int*   user_ids       = (const int*)  d_in[7];
    const int*   item_ids       = (const int*)  d_in[8];
    const int*   pos_targets    = (const int*)  d_in[9];
    const int*   pos_lens       = (const int*)  d_in[10];
    const int*   neg_targets    = (const int*)  d_in[11];
    const int*   neg_lens       = (const int*)  d_in[12];
    const float* attr_emb       = (const float*)d_in[13];
    const float* user_emb       = (const float*)d_in[14];
    const float* item_emb       = (const float*)d_in[15];
    const float* out_emb        = (const float*)d_in[16];
    const float* fw_W           = (const float*)d_in[17];
    const float* fw_b           = (const float*)d_in[18];
    const float* qkv_w          = (const float*)d_in[19];
    const float* qkv_b          = (const float*)d_in[20];
    const float* attn_out_w     = (const float*)d_in[21];
    const float* attn_out_b     = (const float*)d_in[22];
    const float* ln1_s          = (const float*)d_in[23];
    const float* ln1_b          = (const float*)d_in[24];
    const float* ff1_w          = (const float*)d_in[25];
    const float* ff1_b          = (const float*)d_in[26];
    const float* ff2_w          = (const float*)d_in[27];
    const float* ff2_b          = (const float*)d_in[28];
    const float* ln2_s          = (const float*)d_in[29];
    const float* ln2_b          = (const float*)d_in[30];

    float *x, *qkv, *attn, *tmp, *ff, *outv, *wr;
    cudaGetSymbolAddress((void**)&x,    g_x);
    cudaGetSymbolAddress((void**)&qkv,  g_qkv);
    cudaGetSymbolAddress((void**)&attn, g_attn);
    cudaGetSymbolAddress((void**)&tmp,  g_tmp);
    cudaGetSymbolAddress((void**)&ff,   g_ff);
    cudaGetSymbolAddress((void**)&outv, g_out);
    cudaGetSymbolAddress((void**)&wr,   g_wr);

    const int gemm_smem = STAGES * 2 * TSZ * (int)sizeof(float);   // 61440
    cudaFuncSetAttribute(tgemm<false, true>, cudaFuncAttributeMaxDynamicSharedMemorySize,
                         gemm_smem);
    cudaFuncSetAttribute(tgemm<false, false>, cudaFuncAttributeMaxDynamicSharedMemorySize,
                         gemm_smem);
    cudaFuncSetAttribute(tgemm<true, true>, cudaFuncAttributeMaxDynamicSharedMemorySize,
                         gemm_smem);
    const int attn_smem = ATTN_SMEMF * (int)sizeof(float);         // 105984
    cudaFuncSetAttribute(attn_kernel, cudaFuncAttributeMaxDynamicSharedMemorySize,
                         attn_smem);

    round_w_kernel<<<1536, 256>>>((const float4*)qkv_w, (const float4*)attn_out_w,
                                  (const float4*)ff1_w, (const float4*)ff2_w,
                                  (float4*)wr);
    gather_kernel<<<(T_ * E_ / 4 + 255) / 256, 256>>>(attr, attr_emb, x);

    for (int l = 0; l < L_; l++) {
        const float* lqkv_w = wr + WR_QKV + (size_t)l * 3 * E_ * E_;
        const float* lao_w  = wr + WR_AO  + (size_t)l * E_ * E_;
        const float* lf1_w  = wr + WR_FF1 + (size_t)l * F_ * E_;
        const float* lf2_w  = wr + WR_FF2 + (size_t)l * E_ * F_;
        const float* lqkv_b = qkv_b      + (size_t)l * 3 * E_;
        const float* lao_b  = attn_out_b + (size_t)l * E_;
        const float* l1s    = ln1_s + (size_t)l * E_;
        const float* l1b    = ln1_b + (size_t)l * E_;
        const float* lf1_b  = ff1_b + (size_t)l * F_;
        const float* lf2_b  = ff2_b + (size_t)l * E_;
        const float* l2s    = ln2_s + (size_t)l * E_;
        const float* l2b    = ln2_b + (size_t)l * E_;

        tgemm<false, true><<<dim3(3 * E_ / 128, T_ / 128), 256, gemm_smem>>>(
            x, lqkv_w, lqkv_b, qkv, T_, 3 * E_, E_);
        attn_kernel<<<B_ * H_, 512, attn_smem>>>(qkv, attr_lens, attn);
        tgemm<false, false><<<dim3(E_ / 128, T_ / 128), 256, gemm_smem>>>(
            attn, lao_w, lao_b, tmp, T_, E_, E_);
        add_ln_kernel<<<T_ / 8, 256>>>(x, tmp, l1s, l1b, x);
        tgemm<true, true><<<dim3(F_ / 128, T_ / 128), 256, gemm_smem>>>(
            x, lf1_w, lf1_b, ff, T_, F_, E_);
        tgemm<false, false><<<dim3(E_ / 128, T_ / 128), 256, gemm_smem>>>(
            ff, lf2_w, lf2_b, tmp, T_, E_, F_);
        add_ln_kernel<<<T_ / 8, 256>>>(x, tmp, l2s, l2b, x);
    }

    pool_kernel<<<B_, 256>>>(x, attr_tf, attr_lens, attr_lens_user,
                             attr_feat, fw_W, fw_b,
                             user_ids, item_ids, user_emb, item_emb, outv);

    const int nwarps = B_ * NTH_;                      // 76800
    logits_kernel<<<(nwarps * 32 + 255) / 256, 256>>>(
        outv, out_emb, pos_targets, pos_lens, neg_targets, neg_lens,
        (float*)d_out);
}

// round 14
// speedup vs baseline: 1.8259x; 1.6338x over previous
#include <cuda_runtime.h>
#include <cuda_fp16.h>
#include <math.h>
#include <stdint.h>

// Problem constants
#define B_   256
#define S_   128
#define P_   100
#define N_   500
#define E_   256
#define H_   4
#define HD_  64
#define L_   2
#define F_   1024
#define T_   (B_ * S_)      // 32768 tokens
#define NT_  (P_ + N_)      // 600 targets
#define NTH_ (NT_ / 2)      // 300 pairs per sample

// ---------------------------------------------------------------------------
// Scratch (device globals — no allocation allowed). Activations in fp16.
// ---------------------------------------------------------------------------
__device__ __half g_x   [(size_t)T_ * E_];
__device__ __half g_qkv [(size_t)T_ * 3 * E_];
__device__ __half g_attn[(size_t)T_ * E_];
__device__ __half g_tmp [(size_t)T_ * E_];
__device__ __half g_ff  [(size_t)T_ * F_];
__device__ float  g_out [(size_t)B_ * 3 * E_];
__device__ __half g_wh  [1572864];            // fp16 weights (3MB)

// half-element offsets into g_wh
#define WR_QKV 0
#define WR_AO  393216
#define WR_FF1 524288
#define WR_FF2 1048576

// ---------------------------------------------------------------------------
// helpers
// ---------------------------------------------------------------------------
__device__ __forceinline__ void cp16(void* sdst, const void* gsrc) {
    uint32_t s = (uint32_t)__cvta_generic_to_shared(sdst);
    asm volatile("cp.async.cg.shared.global [%0], [%1], 16;\n" :: "r"(s), "l"(gsrc));
}
__device__ __forceinline__ void cp_commit() {
    asm volatile("cp.async.commit_group;\n");
}
template<int NWait>
__device__ __forceinline__ void cp_wait() {
    asm volatile("cp.async.wait_group %0;\n" :: "n"(NWait));
}
__device__ __forceinline__ uint32_t f22h2(float a, float b) {
    __half2 h = __floats2half2_rn(a, b);
    return *(uint32_t*)&h;
}
__device__ __forceinline__ float2 h22f2(uint32_t u) {
    return __half22float2(*(__half2*)&u);
}
#define MMA_F16(d, a, b)                                                      \
    asm volatile(                                                             \
        "mma.sync.aligned.m16n8k16.row.col.f32.f16.f16.f32 "                  \
        "{%0,%1,%2,%3}, {%4,%5,%6,%7}, {%8,%9}, {%0,%1,%2,%3};"               \
        : "+f"(d[0]), "+f"(d[1]), "+f"(d[2]), "+f"(d[3])                      \
        : "r"(a[0]), "r"(a[1]), "r"(a[2]), "r"(a[3]), "r"(b[0]), "r"(b[1]))

// ---------------------------------------------------------------------------
// Weight conversion fp32 -> fp16 (once per launch)
// ---------------------------------------------------------------------------
__global__ void conv_w_kernel(const float4* __restrict__ qkvw,
                              const float4* __restrict__ aow,
                              const float4* __restrict__ f1w,
                              const float4* __restrict__ f2w,
                              uint32_t* __restrict__ dst) {
    const int i = blockIdx.x * blockDim.x + threadIdx.x;
    if (i >= 393216) return;
    float4 v;
    int o = i;
    if (o < 98304)                  v = qkvw[o];
    else if ((o -= 98304) < 32768)  v = aow[o];
    else if ((o -= 32768) < 131072) v = f1w[o];
    else                            v = f2w[o - 131072];
    dst[2 * i]     = f22h2(v.x, v.y);
    dst[2 * i + 1] = f22h2(v.z, v.w);
}

// ---------------------------------------------------------------------------
// Embedding gather: fp32 emb -> fp16 x. Thread handles 8 halves.
// ---------------------------------------------------------------------------
__global__ void gather_kernel(const int* __restrict__ attr,
                              const float* __restrict__ emb,
                              __half* __restrict__ x) {
    int i = blockIdx.x * blockDim.x + threadIdx.x;
    if (i < T_ * (E_ / 8)) {
        int t  = i >> 5;
        int e8 = i & 31;
        const float4* src = (const float4*)(emb + (size_t)attr[t] * E_) + e8 * 2;
        float4 v0 = src[0], v1 = src[1];
        uint4 o;
        o.x = f22h2(v0.x, v0.y); o.y = f22h2(v0.z, v0.w);
        o.z = f22h2(v1.x, v1.y); o.w = f22h2(v1.z, v1.w);
        *(uint4*)(x + (size_t)t * E_ + e8 * 8) = o;
    }
}

// ---------------------------------------------------------------------------
// FP16 tensor-core GEMM: C = A @ B^T + bias (opt ReLU), fp32 accum.
// Block 128x128, BK=16 halves (one m16n8k16 step), 8 warps of 64x32,
// 3-stage cp.async, 2 CTAs/SM. Smem rows: 16 halves = 8 u32 + 4 pad (LDW=12,
// bank = 12*row mod 32 = {0,12,24,4,16,28,8,20} -> conflict-free fragments).
// ---------------------------------------------------------------------------
#define LDW    12
#define TSZ    (128 * LDW)     // u32 per matrix per stage
#define STAGES 3

template<bool RELU>
__global__ __launch_bounds__(256, 2)
void hgemm(const __half* __restrict__ A, const __half* __restrict__ Bm,
           const float* __restrict__ bias, __half* __restrict__ C,
           int M, int N, int K) {
    extern __shared__ uint32_t smh[];
    uint32_t* As = smh;
    uint32_t* Bs = smh + STAGES * TSZ;

    const int bm   = blockIdx.y * 128;
    const int bn   = blockIdx.x * 128;
    const int t    = threadIdx.x;
    const int lane = t & 31;
    const int wid  = t >> 5;
    const int wm   = (wid & 1) * 64;
    const int wn   = (wid >> 1) * 32;
    const int g    = lane >> 2;
    const int tg   = lane & 3;

    const int lrow = t >> 1;            // 0..127
    const int lk   = (t & 1);           // which 8-half chunk
    const __half* Ap = A  + (size_t)(bm + lrow) * K + lk * 8;
    const __half* Bp = Bm + (size_t)(bn + lrow) * K + lk * 8;

    float acc[4][4][4];
#pragma unroll
    for (int i = 0; i < 4; i++)
#pragma unroll
        for (int j = 0; j < 4; j++)
#pragma unroll
            for (int r = 0; r < 4; r++) acc[i][j][r] = 0.f;

    const int nk = K >> 4;
#pragma unroll
    for (int s = 0; s < STAGES - 1; s++) {
        const int k0 = s << 4;
        cp16(&As[s * TSZ + lrow * LDW + lk * 4], Ap + k0);
        cp16(&Bs[s * TSZ + lrow * LDW + lk * 4], Bp + k0);
        cp_commit();
    }

    int cur = 0;
    for (int kt = 0; kt < nk; kt++) {
        if (kt < nk - 1) cp_wait<STAGES - 2>(); else cp_wait<0>();
        __syncthreads();

        const uint32_t* Ac = As + cur * TSZ;
        const uint32_t* Bc = Bs + cur * TSZ;
        uint32_t af[4][4], bf[4][2];
#pragma unroll
        for (int mf = 0; mf < 4; mf++) {
            const int row = wm + mf * 16 + g;
            af[mf][0] = Ac[row * LDW + tg];
            af[mf][1] = Ac[(row + 8) * LDW + tg];
            af[mf][2] = Ac[row * LDW + tg + 4];
            af[mf][3] = Ac[(row + 8) * LDW + tg + 4];
        }
#pragma unroll
        for (int nf = 0; nf < 4; nf++) {
            const int col = wn + nf * 8 + g;
            bf[nf][0] = Bc[col * LDW + tg];
            bf[nf][1] = Bc[col * LDW + tg + 4];
        }
#pragma unroll
        for (int mf = 0; mf < 4; mf++)
#pragma unroll
            for (int nf = 0; nf < 4; nf++) MMA_F16(acc[mf][nf], af[mf], bf[nf]);

        const int pf = kt + STAGES - 1;
        if (pf < nk) {
            const int ps = pf % STAGES;
            const int k0 = pf << 4;
            cp16(&As[ps * TSZ + lrow * LDW + lk * 4], Ap + k0);
            cp16(&Bs[ps * TSZ + lrow * LDW + lk * 4], Bp + k0);
            cp_commit();
        }
        cur = (cur + 1 == STAGES) ? 0 : cur + 1;
    }

    // epilogue: bias (+ReLU), half2 stores
#pragma unroll
    for (int nf = 0; nf < 4; nf++) {
        const int col = bn + wn + nf * 8 + 2 * tg;
        const float b0v = bias[col], b1v = bias[col + 1];
#pragma unroll
        for (int mf = 0; mf < 4; mf++) {
            const int row = bm + wm + mf * 16 + g;
            float v0 = acc[mf][nf][0] + b0v;
            float v1 = acc[mf][nf][1] + b1v;
            float v2 = acc[mf][nf][2] + b0v;
            float v3 = acc[mf][nf][3] + b1v;
            if (RELU) {
                v0 = fmaxf(v0, 0.f); v1 = fmaxf(v1, 0.f);
                v2 = fmaxf(v2, 0.f); v3 = fmaxf(v3, 0.f);
            }
            *(uint32_t*)(C + (size_t)row * N + col)       = f22h2(v0, v1);
            *(uint32_t*)(C + (size_t)(row + 8) * N + col) = f22h2(v2, v3);
        }
    }
}

// ---------------------------------------------------------------------------
// FP16 tensor-core attention: one block per (b,h), 512 threads (16 warps).
// Phase 1: S=Q@K^T (k16 MMA, 4 steps). Phase 2: O=P@V (8 steps).
// smem u32 units: Vt 64x68 | Q 128x36 | K 128x36 (P 128x68 overlays Q+K)
// ---------------------------------------------------------------------------
#define QLD2 36
#define PLD3 68
#define VT_OFF 0
#define Q_OFF  (64 * PLD3)                 // 4352
#define K_OFF  (Q_OFF + 128 * QLD2)        // 8960
#define P_OFF  Q_OFF                       // 4352..13056 <= 13568
#define PART_OFF (K_OFF + 128 * QLD2)      // 13568 (float units)
#define RSUM_OFF (PART_OFF + 512)          // 14080
#define ATTN_SMEMU (RSUM_OFF + 128)        // 14208 u32 = 56832 B

__global__ __launch_bounds__(512)
void attn_kernel(const __half* __restrict__ qkv,
                 const int* __restrict__ lens,
                 __half* __restrict__ out) {
    const int bh = blockIdx.x;
    const int b  = bh / H_;
    const int h  = bh % H_;
    extern __shared__ uint32_t smu[];
    float*  smf = (float*)smu;
    __half* smx = (__half*)smu;

    const int t    = threadIdx.x;
    const int lane = t & 31;
    const int wid  = t >> 5;
    const int g    = lane >> 2;
    const int tg   = lane & 3;
    const int len  = lens[b];

    // load: Q,K rows (8 halves per float4 chunk), V transposed to Vt[d][s]
    for (int i4 = t; i4 < S_ * 8; i4 += 512) {
        const int s  = i4 >> 3;
        const int d8 = i4 & 7;
        const float4* base =
            (const float4*)(qkv + (size_t)(b * S_ + s) * (3 * E_) + h * HD_);
        float4 qv = base[d8];
        float4 kv = base[32 + d8];         // +256 halves
        float4 vv = base[64 + d8];         // +512 halves
        *(float4*)&smu[Q_OFF + s * QLD2 + d8 * 4] = qv;
        *(float4*)&smu[K_OFF + s * QLD2 + d8 * 4] = kv;
        const __half* vh = (const __half*)&vv;
        const int d0 = d8 * 8;
#pragma unroll
        for (int j = 0; j < 8; j++)
            smx[(d0 + j) * (PLD3 * 2) + s] = vh[j];
    }
    __syncthreads();

    // ---- phase 1: warp tile 32(q) x 32(k), 4x4 warp grid, 4 k16 steps ----
    const int wm = (wid & 3) * 32;
    const int wn = (wid >> 2) * 32;
    float acc[2][4][4];
#pragma unroll
    for (int i = 0; i < 2; i++)
#pragma unroll
        for (int j = 0; j < 4; j++)
#pragma unroll
            for (int r = 0; r < 4; r++) acc[i][j][r] = 0.f;

#pragma unroll
    for (int ks = 0; ks < 4; ks++) {
        const int k2 = ks * 8;    // u32 per k16
        uint32_t af[2][4], bf[4][2];
#pragma unroll
        for (int mf = 0; mf < 2; mf++) {
            const int row = wm + mf * 16 + g;
            af[mf][0] = smu[Q_OFF + row * QLD2 + k2 + tg];
            af[mf][1] = smu[Q_OFF + (row + 8) * QLD2 + k2 + tg];
            af[mf][2] = smu[Q_OFF + row * QLD2 + k2 + tg + 4];
            af[mf][3] = smu[Q_OFF + (row + 8) * QLD2 + k2 + tg + 4];
        }
#pragma unroll
        for (int nf = 0; nf < 4; nf++) {
            const int col = wn + nf * 8 + g;
            bf[nf][0] = smu[K_OFF + col * QLD2 + k2 + tg];
            bf[nf][1] = smu[K_OFF + col * QLD2 + k2 + tg + 4];
        }
#pragma unroll
        for (int mf = 0; mf < 2; mf++)
#pragma unroll
            for (int nf = 0; nf < 4; nf++) MMA_F16(acc[mf][nf], af[mf], bf[nf]);
    }

    // exp + row partial sums
    float rs[2][2];
#pragma unroll
    for (int mf = 0; mf < 2; mf++) { rs[mf][0] = 0.f; rs[mf][1] = 0.f; }
#pragma unroll
    for (int mf = 0; mf < 2; mf++) {
#pragma unroll
        for (int nf = 0; nf < 4; nf++) {
            const int c0 = wn + nf * 8 + 2 * tg;
            const int c1 = c0 + 1;
            float* d = acc[mf][nf];
            d[0] = (c0 < len) ? __expf(d[0] * 0.125f) : 0.f;
            d[1] = (c1 < len) ? __expf(d[1] * 0.125f) : 0.f;
            d[2] = (c0 < len) ? __expf(d[2] * 0.125f) : 0.f;
            d[3] = (c1 < len) ? __expf(d[3] * 0.125f) : 0.f;
            rs[mf][0] += d[0] + d[1];
            rs[mf][1] += d[2] + d[3];
        }
#pragma unroll
        for (int o = 1; o < 4; o <<= 1) {
            rs[mf][0] += __shfl_xor_sync(0xffffffffu, rs[mf][0], o);
            rs[mf][1] += __shfl_xor_sync(0xffffffffu, rs[mf][1], o);
        }
    }
    __syncthreads();   // Q/K reads done -> overlay P

    const int nidx = wid >> 2;
#pragma unroll
    for (int mf = 0; mf < 2; mf++) {
        const int r0 = wm + mf * 16 + g;
        const int r1 = r0 + 8;
#pragma unroll
        for (int nf = 0; nf < 4; nf++) {
            const int c2 = (wn >> 1) + nf * 4 + tg;   // half2 index of col c0
            const float* d = acc[mf][nf];
            smu[P_OFF + r0 * PLD3 + c2] = f22h2(d[0], d[1]);
            smu[P_OFF + r1 * PLD3 + c2] = f22h2(d[2], d[3]);
        }
        if (tg == 0) {
            smf[PART_OFF + r0 * 4 + nidx] = rs[mf][0];
            smf[PART_OFF + r1 * 4 + nidx] = rs[mf][1];
        }
    }
    __syncthreads();

    if (t < 128) {
        const float s = smf[PART_OFF + t * 4] + smf[PART_OFF + t * 4 + 1] +
                        smf[PART_OFF + t * 4 + 2] + smf[PART_OFF + t * 4 + 3];
        smf[RSUM_OFF + t] = 1.f / s;
    }
    __syncthreads();

    // ---- phase 2: warp tile 16(q) x 32(d), 8x2 warp grid, 8 k16 steps ----
    const int wm2 = (wid & 7) * 16;
    const int wn2 = (wid >> 3) * 32;
    float acc2[4][4];
#pragma unroll
    for (int j = 0; j < 4; j++)
#pragma unroll
        for (int r = 0; r < 4; r++) acc2[j][r] = 0.f;

#pragma unroll
    for (int ks = 0; ks < 8; ks++) {
        const int k2 = ks * 8;
        uint32_t af[4], bf[4][2];
        {
            const int row = wm2 + g;
            af[0] = smu[P_OFF + row * PLD3 + k2 + tg];
            af[1] = smu[P_OFF + (row + 8) * PLD3 + k2 + tg];
            af[2] = smu[P_OFF + row * PLD3 + k2 + tg + 4];
            af[3] = smu[P_OFF + (row + 8) * PLD3 + k2 + tg + 4];
        }
#pragma unroll
        for (int nf = 0; nf < 4; nf++) {
            const int col = wn2 + nf * 8 + g;
            bf[nf][0] = smu[VT_OFF + col * PLD3 + k2 + tg];
            bf[nf][1] = smu[VT_OFF + col * PLD3 + k2 + tg + 4];
        }
#pragma unroll
        for (int nf = 0; nf < 4; nf++) MMA_F16(acc2[nf], af, bf[nf]);
    }

    // normalize + store (half2)
    {
        const int r0 = wm2 + g;
        const int r1 = r0 + 8;
        const float i0 = smf[RSUM_OFF + r0];
        const float i1 = smf[RSUM_OFF + r1];
#pragma unroll
        for (int nf = 0; nf < 4; nf++) {
            const int c = wn2 + nf * 8 + 2 * tg;
            const float* d = acc2[nf];
            *(uint32_t*)(out + (size_t)(b * S_ + r0) * E_ + h * HD_ + c) =
                f22h2(d[0] * i0, d[1] * i0);
            *(uint32_t*)(out + (size_t)(b * S_ + r1) * E_ + h * HD_ + c) =
                f22h2(d[2] * i1, d[3] * i1);
        }
    }
}

// ---------------------------------------------------------------------------
// Fused residual add + LayerNorm (fp16 in/out, fp32 math): warp per token
// ---------------------------------------------------------------------------
__global__ __launch_bounds__(256)
void add_ln_kernel(const __half* __restrict__ x, const __half* __restrict__ y,
                   const float* __restrict__ sc, const float* __restrict__ bi,
                   __half* __restrict__ out) {
    const int tok  = blockIdx.x * 8 + (threadIdx.x >> 5);
    const int lane = threadIdx.x & 31;

    uint4 xv = ((const uint4*)(x + (size_t)tok * E_))[lane];
    uint4 yv = ((const uint4*)(y + (size_t)tok * E_))[lane];
    float2 v[4];
    {
        float2 a, c;
        a = h22f2(xv.x); c = h22f2(yv.x); v[0] = make_float2(a.x + c.x, a.y + c.y);
        a = h22f2(xv.y); c = h22f2(yv.y); v[1] = make_float2(a.x + c.x, a.y + c.y);
        a = h22f2(xv.z); c = h22f2(yv.z); v[2] = make_float2(a.x + c.x, a.y + c.y);
        a = h22f2(xv.w); c = h22f2(yv.w); v[3] = make_float2(a.x + c.x, a.y + c.y);
    }
    float s = 0.f;
#pragma unroll
    for (int i = 0; i < 4; i++) s += v[i].x + v[i].y;
#pragma unroll
    for (int o = 16; o; o >>= 1) s += __shfl_xor_sync(0xffffffffu, s, o);
    const float m = s * (1.f / E_);

    float q = 0.f;
#pragma unroll
    for (int i = 0; i < 4; i++) {
        q += (v[i].x - m) * (v[i].x - m) + (v[i].y - m) * (v[i].y - m);
    }
#pragma unroll
    for (int o = 16; o; o >>= 1) q += __shfl_xor_sync(0xffffffffu, q, o);
    const float rstd = rsqrtf(q * (1.f / E_) + 1e-5f);

    const float4 s0 = ((const float4*)sc)[lane * 2];
    const float4 s1 = ((const float4*)sc)[lane * 2 + 1];
    const float4 b0 = ((const float4*)bi)[lane * 2];
    const float4 b1 = ((const float4*)bi)[lane * 2 + 1];
    uint4 o;
    o.x = f22h2((v[0].x - m) * rstd * s0.x + b0.x,
                (v[0].y - m) * rstd * s0.y + b0.y);
    o.y = f22h2((v[1].x - m) * rstd * s0.z + b0.z,
                (v[1].y - m) * rstd * s0.w + b0.w);
    o.z = f22h2((v[2].x - m) * rstd * s1.x + b1.x,
                (v[2].y - m) * rstd * s1.y + b1.y);
    o.w = f22h2((v[3].x - m) * rstd * s1.z + b1.z,
                (v[3].y - m) * rstd * s1.w + b1.w);
    ((uint4*)(out + (size_t)tok * E_))[lane] = o;
}

// ---------------------------------------------------------------------------
// Weighted pool + concat (+ sigmoid gate); x fp16, outv fp32
// ---------------------------------------------------------------------------
__global__ __launch_bounds__(256)
void pool_kernel(const __half* __restrict__ x, const float* __restrict__ attr_tf,
                 const int* __restrict__ lens, const int* __restrict__ lens_user,
                 const float* __restrict__ feat, const float* __restrict__ fW,
                 const float* __restrict__ fb,
                 const int* __restrict__ user_ids, const int* __restrict__ item_ids,
                 const float* __restrict__ user_emb, const float* __restrict__ item_emb,
                 float* __restrict__ out) {
    const int b = blockIdx.x;
    const int e = threadIdx.x;
    __shared__ float w[S_];
    __shared__ float wu_s;
    if (e == 0) {
        float z = fb[0];
#pragma unroll
        for (int i = 0; i < 13; i++) z += feat[b * 13 + i] * fW[i];
        wu_s = 1.f / (1.f + expf(-z));
    }
    __syncthreads();
    if (e < S_) {
        const int s = e;
        float wgt = 0.f;
        if (s < lens[b]) {
            const float g = (s < lens_user[b]) ? wu_s : (1.f - wu_s);
            wgt = attr_tf[b * S_ + s] * g;
        }
        w[s] = wgt;
    }
    __syncthreads();
    float acc = 0.f;
    const __half* xb = x + (size_t)b * S_ * E_ + e;
    for (int s = 0; s < S_; s++) acc += w[s] * __half2float(xb[(size_t)s * E_]);
    out[(size_t)b * 3 * E_ + E_ + e]     = acc;
    out[(size_t)b * 3 * E_ + e]          = user_emb[(size_t)user_ids[b] * E_ + e];
    out[(size_t)b * 3 * E_ + 2 * E_ + e] = item_emb[(size_t)item_ids[b] * E_ + e];
}

// ---------------------------------------------------------------------------
// Scoring head: one warp per PAIR of targets (j, j+300); fp32 throughout
// ---------------------------------------------------------------------------
__global__ __launch_bounds__(256)
void logits_kernel(const float* __restrict__ outv, const float* __restrict__ out_emb,
                   const int* __restrict__ pos_t, const int* __restrict__ pos_l,
                   const int* __restrict__ neg_t, const int* __restrict__ neg_l,
                   float* __restrict__ dout) {
    const int gw   = (int)((blockIdx.x * blockDim.x + threadIdx.x) >> 5);
    const int lane = threadIdx.x & 31;
    if (gw >= B_ * NTH_) return;
    const int b  = gw / NTH_;
    const int j1 = gw % NTH_;
    const int j2 = j1 + NTH_;

    const int pl = pos_l[b];
    const int nl = neg_l[b];

    int tgt1; float valid1, posf1;
    if (j1 < P_) {
        tgt1 = pos_t[b * P_ + j1]; valid1 = (j1 < pl) ? 1.f : 0.f; posf1 = 1.f;
    } else {
        const int jn = j1 - P_;
        tgt1 = neg_t[b * N_ + jn]; valid1 = (jn < nl) ? 1.f : 0.f; posf1 = 0.f;
    }
    int tgt2; float valid2, posf2;
    {
        const int jn = j2 - P_;
        tgt2 = neg_t[b * N_ + jn]; valid2 = (jn < nl) ? 1.f : 0.f; posf2 = 0.f;
    }

    const float4* ovs = (const float4*)(outv + (size_t)b * (3 * E_));
    const float4* e1  = (const float4*)(out_emb + (size_t)tgt1 * (3 * E_));
    const float4* e2  = (const float4*)(out_emb + (size_t)tgt2 * (3 * E_));
    float a1 = 0.f, a2 = 0.f;
#pragma unroll
    for (int i = 0; i < 6; i++) {
        const int k4 = lane + i * 32;
        const float4 c  = ovs[k4];
        const float4 r1 = e1[k4];
        const float4 r2 = e2[k4];
        a1 += r1.x * c.x + r1.y * c.y + r1.z * c.z + r1.w * c.w;
        a2 += r2.x * c.x + r2.y * c.y + r2.z * c.z + r2.w * c.w;
    }
#pragma unroll
    for (int o = 16; o; o >>= 1) {
        a1 += __shfl_xor_sync(0xffffffffu, a1, o);
        a2 += __shfl_xor_sync(0xffffffffu, a2, o);
    }
    if (lane == 0) {
        const int idx1 = b * NT_ + j1;
        const int idx2 = b * NT_ + j2;
        dout[idx1]                = a1;
        dout[B_ * NT_ + idx1]     = valid1;
        dout[2 * B_ * NT_ + idx1] = posf1 * valid1;
        dout[idx2]                = a2;
        dout[B_ * NT_ + idx2]     = valid2;
        dout[2 * B_ * NT_ + idx2] = posf2 * valid2;
    }
}

// ---------------------------------------------------------------------------
// Launch
// ---------------------------------------------------------------------------
extern "C" void kernel_launch(void* const* d_in, const int* in_sizes, int n_in,
                              void* d_out, int out_size) {
    const int*   attr           = (const int*)  d_in[0];
    const float* attr_tf        = (const float*)d_in[2];
    const float* attr_feat      = (const float*)d_in[3];
    const int*   attr_lens      = (const int*)  d_in[4];
    const int*   attr_lens_user = (const int*)  d_in[5];
    const int*   user_ids       = (const int*)  d_in[7];
    const int*   item_ids       = (const int*)  d_in[8];
    const int*   pos_targets    = (const int*)  d_in[9];
    const int*   pos_lens       = (const int*)  d_in[10];
    const int*   neg_targets    = (const int*)  d_in[11];
    const int*   neg_lens       = (const int*)  d_in[12];
    const float* attr_emb       = (const float*)d_in[13];
    const float* user_emb       = (const float*)d_in[14];
    const float* item_emb       = (const float*)d_in[15];
    const float* out_emb        = (const float*)d_in[16];
    const float* fw_W           = (const float*)d_in[17];
    const float* fw_b           = (const float*)d_in[18];
    const float* qkv_w          = (const float*)d_in[19];
    const float* qkv_b          = (const float*)d_in[20];
    const float* attn_out_w     = (const float*)d_in[21];
    const float* attn_out_b     = (const float*)d_in[22];
    const float* ln1_s          = (const float*)d_in[23];
    const float* ln1_b          = (const float*)d_in[24];
    const float* ff1_w          = (const float*)d_in[25];
    const float* ff1_b          = (const float*)d_in[26];
    const float* ff2_w          = (const float*)d_in[27];
    const float* ff2_b          = (const float*)d_in[28];
    const float* ln2_s          = (const float*)d_in[29];
    const float* ln2_b          = (const float*)d_in[30];

    __half *x, *qkv, *attn, *tmp, *ff, *wh;
    float *outv;
    cudaGetSymbolAddress((void**)&x,    g_x);
    cudaGetSymbolAddress((void**)&qkv,  g_qkv);
    cudaGetSymbolAddress((void**)&attn, g_attn);
    cudaGetSymbolAddress((void**)&tmp,  g_tmp);
    cudaGetSymbolAddress((void**)&ff,   g_ff);
    cudaGetSymbolAddress((void**)&outv, g_out);
    cudaGetSymbolAddress((void**)&wh,   g_wh);

    const int gemm_smem = STAGES * 2 * TSZ * (int)sizeof(uint32_t);   // 36864
    cudaFuncSetAttribute(hgemm<false>, cudaFuncAttributeMaxDynamicSharedMemorySize,
                         gemm_smem);
    cudaFuncSetAttribute(hgemm<true>, cudaFuncAttributeMaxDynamicSharedMemorySize,
                         gemm_smem);
    const int attn_smem = ATTN_SMEMU * (int)sizeof(uint32_t);         // 56832
    cudaFuncSetAttribute(attn_kernel, cudaFuncAttributeMaxDynamicSharedMemorySize,
                         attn_smem);

    conv_w_kernel<<<1536, 256>>>((const float4*)qkv_w, (const float4*)attn_out_w,
                                 (const float4*)ff1_w, (const float4*)ff2_w,
                                 (uint32_t*)wh);
    gather_kernel<<<(T_ * E_ / 8 + 255) / 256, 256>>>(attr, attr_emb, x);

    for (int l = 0; l < L_; l++) {
        const __half* lqkv_w = wh + WR_QKV + (size_t)l * 3 * E_ * E_;
        const __half* lao_w  = wh + WR_AO  + (size_t)l * E_ * E_;
        const __half* lf1_w  = wh + WR_FF1 + (size_t)l * F_ * E_;
        const __half* lf2_w  = wh + WR_FF2 + (size_t)l * E_ * F_;
        const float* lqkv_b = qkv_b      + (size_t)l * 3 * E_;
        const float* lao_b  = attn_out_b + (size_t)l * E_;
        const float* l1s    = ln1_s + (size_t)l * E_;
        const float* l1b    = ln1_b + (size_t)l * E_;
        const float* lf1_b  = ff1_b + (size_t)l * F_;
        const float* lf2_b  = ff2_b + (size_t)l * E_;
        const float* l2s    = ln2_s + (size_t)l * E_;
        const float* l2b    = ln2_b + (size_t)l * E_;

        hgemm<false><<<dim3(3 * E_ / 128, T_ / 128), 256, gemm_smem>>>(
            x, lqkv_w, lqkv_b, qkv, T_, 3 * E_, E_);
        attn_kernel<<<B_ * H_, 512, attn_smem>>>(qkv, attr_lens, attn);
        hgemm<false><<<dim3(E_ / 128, T_ / 128), 256, gemm_smem>>>(
            attn, lao_w, lao_b, tmp, T_, E_, E_);
        add_ln_kernel<<<T_ / 8, 256>>>(x, tmp, l1s, l1b, x);
        hgemm<true><<<dim3(F_ / 128, T_ / 128), 256, gemm_smem>>>(
            x, lf1_w, lf1_b, ff, T_, F_, E_);
        hgemm<false><<<dim3(E_ / 128, T_ / 128), 256, gemm_smem>>>(
            ff, lf2_w, lf2_b, tmp, T_, E_, F_);
        add_ln_kernel<<<T_ / 8, 256>>>(x, tmp, l2s, l2b, x);
    }

    pool_kernel<<<B_, 256>>>(x, attr_tf, attr_lens, attr_lens_user,
                             attr_feat, fw_W, fw_b,
                             user_ids, item_ids, user_emb, item_emb, outv);

    const int nwarps = B_ * NTH_;                      // 76800
    logits_kernel<<<(nwarps * 32 + 255) / 256, 256>>>(
        outv, out_emb, pos_targets, pos_lens, neg_targets, neg_lens,
        (float*)d_out);
}